// round 1
// baseline (speedup 1.0000x reference)
#include <cuda_runtime.h>
#include <math.h>

// Problem dims (fixed by the reference)
#define Bx   4
#define Tx   2048
#define Mx   2048
#define Dx   1024
#define Hx   16
#define DKx  64
#define DFFx 4096
#define NX   (Bx*Tx)   // 8192 rows of x
#define NM   (Bx*Mx)   // 8192 rows of mem

#define NEGINF (__int_as_float(0xff800000))

// ---------------------------------------------------------------------------
// Scratch (device globals; allocation-free per harness rules)
// ---------------------------------------------------------------------------
__device__ float g_h  [NX * Dx];        // LN outputs / yc
__device__ float g_qkv[NX * 3 * Dx];    // self-attn qkv
__device__ float g_y  [NX * Dx];        // attn out / qc
__device__ float g_x  [NX * Dx];        // running residual
__device__ float g_kv [NM * 2 * Dx];    // cross kv
__device__ float g_ff [NX * DFFx];      // ffn hidden

// ---------------------------------------------------------------------------
// LayerNorm: one block per row, D = 1024, 256 threads (one float4 each)
// ---------------------------------------------------------------------------
__global__ __launch_bounds__(256) void ln_kernel(
    const float* __restrict__ X, const float* __restrict__ w,
    const float* __restrict__ b, float* __restrict__ out)
{
    long long row = blockIdx.x;
    const float* xr = X + row * Dx;
    int t = threadIdx.x;
    float4 v = *(const float4*)(xr + t * 4);
    float s  = v.x + v.y + v.z + v.w;
    float ss = v.x*v.x + v.y*v.y + v.z*v.z + v.w*v.w;
    #pragma unroll
    for (int o = 16; o > 0; o >>= 1) {
        s  += __shfl_xor_sync(0xffffffffu, s, o);
        ss += __shfl_xor_sync(0xffffffffu, ss, o);
    }
    __shared__ float rs[8], rss[8];
    __shared__ float smu, srstd;
    if ((t & 31) == 0) { rs[t >> 5] = s; rss[t >> 5] = ss; }
    __syncthreads();
    if (t == 0) {
        float S = 0.f, SS = 0.f;
        #pragma unroll
        for (int i = 0; i < 8; i++) { S += rs[i]; SS += rss[i]; }
        float mu  = S * (1.0f / Dx);
        float var = SS * (1.0f / Dx) - mu * mu;
        smu = mu; srstd = rsqrtf(var + 1e-5f);
    }
    __syncthreads();
    float mu = smu, r = srstd;
    float4 wv = *(const float4*)(w + t * 4);
    float4 bv = *(const float4*)(b + t * 4);
    float4 o;
    o.x = (v.x - mu) * r * wv.x + bv.x;
    o.y = (v.y - mu) * r * wv.y + bv.y;
    o.z = (v.z - mu) * r * wv.z + bv.z;
    o.w = (v.w - mu) * r * wv.w + bv.w;
    *(float4*)(out + row * Dx + t * 4) = o;
}

// ---------------------------------------------------------------------------
// GEMM: C[M,N] = A[M,K] @ W[K,N] + bias (+gelu) (+residual)
// 64x64 tile, BK=16, 256 threads, 4x4 micro-tile.
// ---------------------------------------------------------------------------
__device__ __forceinline__ float gelu_exact(float v) {
    return 0.5f * v * (1.0f + erff(v * 0.7071067811865476f));
}

__global__ __launch_bounds__(256) void gemm_kernel(
    const float* __restrict__ A, const float* __restrict__ W,
    const float* __restrict__ bias, const float* __restrict__ resid,
    float* __restrict__ C, int K, int N, int dogelu)
{
    __shared__ float AsT[16][65];   // [k][m] transposed for broadcast reads
    __shared__ float Ws[16][68];    // [k][n], padded for float4 reads

    int tid = threadIdx.x;
    int tx = tid & 15, ty = tid >> 4;
    int m0 = blockIdx.y * 64, n0 = blockIdx.x * 64;

    int arow = tid >> 2, akq = (tid & 3) * 4;   // A fill mapping
    int wrow = tid >> 4, wcol = (tid & 15) * 4; // W fill mapping

    float acc[4][4];
    #pragma unroll
    for (int i = 0; i < 4; i++)
        #pragma unroll
        for (int j = 0; j < 4; j++) acc[i][j] = 0.f;

    for (int k0 = 0; k0 < K; k0 += 16) {
        float4 av = *(const float4*)(A + (long long)(m0 + arow) * K + k0 + akq);
        float4 wv = *(const float4*)(W + (long long)(k0 + wrow) * N + n0 + wcol);
        AsT[akq + 0][arow] = av.x;
        AsT[akq + 1][arow] = av.y;
        AsT[akq + 2][arow] = av.z;
        AsT[akq + 3][arow] = av.w;
        *(float4*)&Ws[wrow][wcol] = wv;
        __syncthreads();
        #pragma unroll
        for (int kk = 0; kk < 16; kk++) {
            float a0 = AsT[kk][4 * ty + 0];
            float a1 = AsT[kk][4 * ty + 1];
            float a2 = AsT[kk][4 * ty + 2];
            float a3 = AsT[kk][4 * ty + 3];
            float4 w4 = *(const float4*)&Ws[kk][4 * tx];
            acc[0][0] += a0 * w4.x; acc[0][1] += a0 * w4.y; acc[0][2] += a0 * w4.z; acc[0][3] += a0 * w4.w;
            acc[1][0] += a1 * w4.x; acc[1][1] += a1 * w4.y; acc[1][2] += a1 * w4.z; acc[1][3] += a1 * w4.w;
            acc[2][0] += a2 * w4.x; acc[2][1] += a2 * w4.y; acc[2][2] += a2 * w4.z; acc[2][3] += a2 * w4.w;
            acc[3][0] += a3 * w4.x; acc[3][1] += a3 * w4.y; acc[3][2] += a3 * w4.z; acc[3][3] += a3 * w4.w;
        }
        __syncthreads();
    }

    float4 bv = *(const float4*)(bias + n0 + 4 * tx);
    #pragma unroll
    for (int i = 0; i < 4; i++) {
        long long row = m0 + 4 * ty + i;
        float4 v;
        v.x = acc[i][0] + bv.x;
        v.y = acc[i][1] + bv.y;
        v.z = acc[i][2] + bv.z;
        v.w = acc[i][3] + bv.w;
        if (dogelu) {
            v.x = gelu_exact(v.x); v.y = gelu_exact(v.y);
            v.z = gelu_exact(v.z); v.w = gelu_exact(v.w);
        }
        if (resid) {
            float4 rv = *(const float4*)(resid + row * N + n0 + 4 * tx);
            v.x += rv.x; v.y += rv.y; v.z += rv.z; v.w += rv.w;
        }
        *(float4*)(C + row * N + n0 + 4 * tx) = v;
    }
}

// ---------------------------------------------------------------------------
// Flash attention: block = (b,h) x 64-query tile; BK = 64 keys per step.
// 256 threads, 4x4 micro-tiles, online softmax. Static smem = exactly 48KB.
// KsT buffer is reused as the P (probabilities) buffer between sub-GEMMs.
// ---------------------------------------------------------------------------
__global__ __launch_bounds__(256) void attn_kernel(
    const float* __restrict__ Qp, int ldq, long long qbs,
    const float* __restrict__ Kp, int ldk, long long kbs,
    const float* __restrict__ Vp, int ldv, long long vbs,
    float* __restrict__ Op, int ldo, long long obs,
    const int* __restrict__ maskp, int Mk, int causal)
{
    __shared__ float Qs [64 * 64];   // [q][d]
    __shared__ float KsT[64 * 64];   // [d][key] xor-swizzled; reused as P[q][key]
    __shared__ float Vs [64 * 64];   // [key][d]

    int tid = threadIdx.x;
    int tx = tid & 15, ty = tid >> 4;
    int b = blockIdx.x >> 4, h = blockIdx.x & 15;
    int q0 = blockIdx.y * 64;

    const float* Q  = Qp + b * qbs + h * 64;
    const float* Kb = Kp + b * kbs + h * 64;
    const float* Vb = Vp + b * vbs + h * 64;
    const int*   mk = maskp ? (maskp + (long long)b * Mk) : (const int*)0;

    // Load Q tile (64 rows x 64 d)
    #pragma unroll
    for (int p = 0; p < 4; p++) {
        int idx = tid + 256 * p;
        int r = idx >> 4, c4 = (idx & 15) * 4;
        float4 qv = *(const float4*)(Q + (long long)(q0 + r) * ldq + c4);
        *(float4*)&Qs[r * 64 + c4] = qv;
    }

    float m_i[4], l_i[4], acc[4][4];
    #pragma unroll
    for (int i = 0; i < 4; i++) {
        m_i[i] = -1e30f; l_i[i] = 0.f;
        #pragma unroll
        for (int j = 0; j < 4; j++) acc[i][j] = 0.f;
    }

    int nkt = causal ? (blockIdx.y + 1) : (Mk / 64);
    for (int kt = 0; kt < nkt; kt++) {
        int k0 = kt * 64;
        __syncthreads();   // prior GEMM2 reads done (and Q load on iter 0)

        // Fill KsT (xor-swizzled transpose) and Vs (row-major), coalesced
        #pragma unroll
        for (int p = 0; p < 4; p++) {
            int idx = tid + 256 * p;
            int key = idx >> 4, c4 = (idx & 15) * 4;
            float4 kv = *(const float4*)(Kb + (long long)(k0 + key) * ldk + c4);
            float kvarr[4] = {kv.x, kv.y, kv.z, kv.w};
            #pragma unroll
            for (int e = 0; e < 4; e++) {
                int d = c4 + e;
                KsT[d * 64 + (((key >> 2) ^ (d & 15)) << 2) + (key & 3)] = kvarr[e];
            }
            float4 vv = *(const float4*)(Vb + (long long)(k0 + key) * ldv + c4);
            *(float4*)&Vs[key * 64 + c4] = vv;
        }
        __syncthreads();

        // GEMM1: S = Q @ K^T for this 64x64 tile
        float s[4][4];
        #pragma unroll
        for (int i = 0; i < 4; i++)
            #pragma unroll
            for (int j = 0; j < 4; j++) s[i][j] = 0.f;
        #pragma unroll 16
        for (int d = 0; d < 64; d++) {
            float4 k4 = *(const float4*)&KsT[d * 64 + ((tx ^ (d & 15)) << 2)];
            float a0 = Qs[(4 * ty + 0) * 64 + d];
            float a1 = Qs[(4 * ty + 1) * 64 + d];
            float a2 = Qs[(4 * ty + 2) * 64 + d];
            float a3 = Qs[(4 * ty + 3) * 64 + d];
            s[0][0] += a0 * k4.x; s[0][1] += a0 * k4.y; s[0][2] += a0 * k4.z; s[0][3] += a0 * k4.w;
            s[1][0] += a1 * k4.x; s[1][1] += a1 * k4.y; s[1][2] += a1 * k4.z; s[1][3] += a1 * k4.w;
            s[2][0] += a2 * k4.x; s[2][1] += a2 * k4.y; s[2][2] += a2 * k4.z; s[2][3] += a2 * k4.w;
            s[3][0] += a3 * k4.x; s[3][1] += a3 * k4.y; s[3][2] += a3 * k4.z; s[3][3] += a3 * k4.w;
        }

        // Scale + masks
        bool diag = (causal != 0) && (k0 == q0);
        int mval[4] = {1, 1, 1, 1};
        if (mk) {
            #pragma unroll
            for (int j = 0; j < 4; j++) mval[j] = mk[k0 + 4 * tx + j];
        }
        #pragma unroll
        for (int i = 0; i < 4; i++)
            #pragma unroll
            for (int j = 0; j < 4; j++) {
                float sv = s[i][j] * 0.125f;   // 1/sqrt(64)
                if (diag && (k0 + 4 * tx + j > q0 + 4 * ty + i)) sv = NEGINF;
                if (mk && mval[j] == 0) sv = NEGINF;
                s[i][j] = sv;
            }
        __syncthreads();   // all KsT reads finished before P overwrites it

        // Online softmax update; write P into KsT buffer (plain layout)
        #pragma unroll
        for (int i = 0; i < 4; i++) {
            float rmax = fmaxf(fmaxf(s[i][0], s[i][1]), fmaxf(s[i][2], s[i][3]));
            #pragma unroll
            for (int o = 1; o < 16; o <<= 1)
                rmax = fmaxf(rmax, __shfl_xor_sync(0xffffffffu, rmax, o));
            float mnew = fmaxf(m_i[i], rmax);
            float sc = __expf(m_i[i] - mnew);
            float p0 = __expf(s[i][0] - mnew);
            float p1 = __expf(s[i][1] - mnew);
            float p2 = __expf(s[i][2] - mnew);
            float p3 = __expf(s[i][3] - mnew);
            float rsum = p0 + p1 + p2 + p3;
            #pragma unroll
            for (int o = 1; o < 16; o <<= 1)
                rsum += __shfl_xor_sync(0xffffffffu, rsum, o);
            l_i[i] = l_i[i] * sc + rsum;
            m_i[i] = mnew;
            acc[i][0] *= sc; acc[i][1] *= sc; acc[i][2] *= sc; acc[i][3] *= sc;
            int r = 4 * ty + i;
            KsT[r * 64 + 4 * tx + 0] = p0;
            KsT[r * 64 + 4 * tx + 1] = p1;
            KsT[r * 64 + 4 * tx + 2] = p2;
            KsT[r * 64 + 4 * tx + 3] = p3;
        }
        __syncthreads();

        // GEMM2: O += P @ V
        #pragma unroll 16
        for (int kk = 0; kk < 64; kk++) {
            float4 v4 = *(const float4*)&Vs[kk * 64 + 4 * tx];
            float p0 = KsT[(4 * ty + 0) * 64 + kk];
            float p1 = KsT[(4 * ty + 1) * 64 + kk];
            float p2 = KsT[(4 * ty + 2) * 64 + kk];
            float p3 = KsT[(4 * ty + 3) * 64 + kk];
            acc[0][0] += p0 * v4.x; acc[0][1] += p0 * v4.y; acc[0][2] += p0 * v4.z; acc[0][3] += p0 * v4.w;
            acc[1][0] += p1 * v4.x; acc[1][1] += p1 * v4.y; acc[1][2] += p1 * v4.z; acc[1][3] += p1 * v4.w;
            acc[2][0] += p2 * v4.x; acc[2][1] += p2 * v4.y; acc[2][2] += p2 * v4.z; acc[2][3] += p2 * v4.w;
            acc[3][0] += p3 * v4.x; acc[3][1] += p3 * v4.y; acc[3][2] += p3 * v4.z; acc[3][3] += p3 * v4.w;
        }
    }

    // Normalize and write output
    #pragma unroll
    for (int i = 0; i < 4; i++) {
        float inv = 1.0f / l_i[i];
        float4 o;
        o.x = acc[i][0] * inv; o.y = acc[i][1] * inv;
        o.z = acc[i][2] * inv; o.w = acc[i][3] * inv;
        *(float4*)(Op + b * obs + (long long)(q0 + 4 * ty + i) * ldo + h * 64 + 4 * tx) = o;
    }
}

// ---------------------------------------------------------------------------
// Launch: 12 graph-capturable kernel launches on the default stream
// ---------------------------------------------------------------------------
extern "C" void kernel_launch(void* const* d_in, const int* in_sizes, int n_in,
                              void* d_out, int out_size)
{
    const float* x         = (const float*)d_in[0];
    const float* mem       = (const float*)d_in[1];
    const int*   mem_mask  = (const int*)  d_in[2];
    const float* ln1_w     = (const float*)d_in[3];
    const float* ln1_b     = (const float*)d_in[4];
    const float* sa_qkv_w  = (const float*)d_in[5];
    const float* sa_qkv_b  = (const float*)d_in[6];
    const float* sa_proj_w = (const float*)d_in[7];
    const float* sa_proj_b = (const float*)d_in[8];
    const float* lnm_w     = (const float*)d_in[9];
    const float* lnm_b     = (const float*)d_in[10];
    const float* ca_q_w    = (const float*)d_in[11];
    const float* ca_q_b    = (const float*)d_in[12];
    const float* ca_kv_w   = (const float*)d_in[13];
    const float* ca_kv_b   = (const float*)d_in[14];
    const float* ca_proj_w = (const float*)d_in[15];
    const float* ca_proj_b = (const float*)d_in[16];
    const float* ln2_w     = (const float*)d_in[17];
    const float* ln2_b     = (const float*)d_in[18];
    const float* ff1_w     = (const float*)d_in[19];
    const float* ff1_b     = (const float*)d_in[20];
    const float* ff2_w     = (const float*)d_in[21];
    const float* ff2_b     = (const float*)d_in[22];
    float* out = (float*)d_out;

    float *h, *qkv, *y, *xr, *kv, *ff;
    cudaGetSymbolAddress((void**)&h,   g_h);
    cudaGetSymbolAddress((void**)&qkv, g_qkv);
    cudaGetSymbolAddress((void**)&y,   g_y);
    cudaGetSymbolAddress((void**)&xr,  g_x);
    cudaGetSymbolAddress((void**)&kv,  g_kv);
    cudaGetSymbolAddress((void**)&ff,  g_ff);

    // 1) h = LN(x)
    ln_kernel<<<NX, 256>>>(x, ln1_w, ln1_b, h);
    // 2) qkv = h @ Wqkv + b
    gemm_kernel<<<dim3(3 * Dx / 64, NX / 64), 256>>>(h, sa_qkv_w, sa_qkv_b, 0, qkv, Dx, 3 * Dx, 0);
    // 3) y = causal self-attention(qkv)
    attn_kernel<<<dim3(Bx * Hx, Tx / 64), 256>>>(
        qkv,            3 * Dx, (long long)Tx * 3 * Dx,
        qkv + Dx,       3 * Dx, (long long)Tx * 3 * Dx,
        qkv + 2 * Dx,   3 * Dx, (long long)Tx * 3 * Dx,
        y,              Dx,     (long long)Tx * Dx,
        (const int*)0, Tx, 1);
    // 4) x1 = x + y @ Wproj + b
    gemm_kernel<<<dim3(Dx / 64, NX / 64), 256>>>(y, sa_proj_w, sa_proj_b, x, xr, Dx, Dx, 0);
    // 5) h = LN(x1)
    ln_kernel<<<NX, 256>>>(xr, lnm_w, lnm_b, h);
    // 6) qc = h @ Wq + b   (into g_y)
    gemm_kernel<<<dim3(Dx / 64, NX / 64), 256>>>(h, ca_q_w, ca_q_b, 0, y, Dx, Dx, 0);
    // 7) kv = mem @ Wkv + b
    gemm_kernel<<<dim3(2 * Dx / 64, NM / 64), 256>>>(mem, ca_kv_w, ca_kv_b, 0, kv, Dx, 2 * Dx, 0);
    // 8) yc = cross-attention(qc, kv, mem_mask)  (into g_h)
    attn_kernel<<<dim3(Bx * Hx, Tx / 64), 256>>>(
        y,         Dx,     (long long)Tx * Dx,
        kv,        2 * Dx, (long long)Mx * 2 * Dx,
        kv + Dx,   2 * Dx, (long long)Mx * 2 * Dx,
        h,         Dx,     (long long)Tx * Dx,
        mem_mask, Mx, 0);
    // 9) x2 = x1 + yc @ Wcp + b  (in-place residual)
    gemm_kernel<<<dim3(Dx / 64, NX / 64), 256>>>(h, ca_proj_w, ca_proj_b, xr, xr, Dx, Dx, 0);
    // 10) h = LN(x2)
    ln_kernel<<<NX, 256>>>(xr, ln2_w, ln2_b, h);
    // 11) ff = gelu(h @ W1 + b)
    gemm_kernel<<<dim3(DFFx / 64, NX / 64), 256>>>(h, ff1_w, ff1_b, 0, ff, Dx, DFFx, 1);
    // 12) out = x2 + ff @ W2 + b
    gemm_kernel<<<dim3(Dx / 64, NX / 64), 256>>>(ff, ff2_w, ff2_b, xr, out, DFFx, Dx, 0);
}

// round 2
// speedup vs baseline: 1.9416x; 1.9416x over previous
#include <cuda_runtime.h>
#include <math.h>
#include <stdint.h>

// Problem dims (fixed by the reference)
#define Bx   4
#define Tx   2048
#define Mx   2048
#define Dx   1024
#define Hx   16
#define DKx  64
#define DFFx 4096
#define NX   (Bx*Tx)   // 8192 rows of x
#define NM   (Bx*Mx)   // 8192 rows of mem

#define NEGINF (__int_as_float(0xff800000))

// ---------------------------------------------------------------------------
// Scratch (device globals; allocation-free per harness rules)
// ---------------------------------------------------------------------------
__device__ float g_h  [NX * Dx];        // LN outputs / yc
__device__ float g_qkv[NX * 3 * Dx];    // self-attn qkv
__device__ float g_y  [NX * Dx];        // attn out / qc
__device__ float g_x  [NX * Dx];        // running residual
__device__ float g_kv [NM * 2 * Dx];    // cross kv
__device__ float g_ff [NX * DFFx];      // ffn hidden

// ---------------------------------------------------------------------------
// LayerNorm: one block per row, D = 1024, 256 threads (one float4 each)
// ---------------------------------------------------------------------------
__global__ __launch_bounds__(256) void ln_kernel(
    const float* __restrict__ X, const float* __restrict__ w,
    const float* __restrict__ b, float* __restrict__ out)
{
    long long row = blockIdx.x;
    const float* xr = X + row * Dx;
    int t = threadIdx.x;
    float4 v = *(const float4*)(xr + t * 4);
    float s  = v.x + v.y + v.z + v.w;
    float ss = v.x*v.x + v.y*v.y + v.z*v.z + v.w*v.w;
    #pragma unroll
    for (int o = 16; o > 0; o >>= 1) {
        s  += __shfl_xor_sync(0xffffffffu, s, o);
        ss += __shfl_xor_sync(0xffffffffu, ss, o);
    }
    __shared__ float rs[8], rss[8];
    __shared__ float smu, srstd;
    if ((t & 31) == 0) { rs[t >> 5] = s; rss[t >> 5] = ss; }
    __syncthreads();
    if (t == 0) {
        float S = 0.f, SS = 0.f;
        #pragma unroll
        for (int i = 0; i < 8; i++) { S += rs[i]; SS += rss[i]; }
        float mu  = S * (1.0f / Dx);
        float var = SS * (1.0f / Dx) - mu * mu;
        smu = mu; srstd = rsqrtf(var + 1e-5f);
    }
    __syncthreads();
    float mu = smu, r = srstd;
    float4 wv = *(const float4*)(w + t * 4);
    float4 bv = *(const float4*)(b + t * 4);
    float4 o;
    o.x = (v.x - mu) * r * wv.x + bv.x;
    o.y = (v.y - mu) * r * wv.y + bv.y;
    o.z = (v.z - mu) * r * wv.z + bv.z;
    o.w = (v.w - mu) * r * wv.w + bv.w;
    *(float4*)(out + row * Dx + t * 4) = o;
}

// ---------------------------------------------------------------------------
// TF32 tensor-core GEMM: C[M,N] = A[M,K] @ W[K,N] + bias (+gelu) (+residual)
// 128x128 tile, BK=16, 256 threads (2x4 warp grid, 64x32 warp tiles),
// mma.sync.m16n8k8.tf32, cp.async double buffering. Static smem = 37.9KB.
// ---------------------------------------------------------------------------
#define APAD 20     // A smem row stride (floats): conflict-free fragment LDS
#define BPAD 136    // B smem row stride (floats): conflict-free fragment LDS

__device__ __forceinline__ float gelu_exact(float v) {
    return 0.5f * v * (1.0f + erff(v * 0.7071067811865476f));
}
__device__ __forceinline__ uint32_t f2tf32(float f) {
    uint32_t r;
    asm("cvt.rna.tf32.f32 %0, %1;\n" : "=r"(r) : "f"(f));
    return r;
}
__device__ __forceinline__ void cp16(uint32_t dst, const void* src) {
    asm volatile("cp.async.cg.shared.global [%0], [%1], 16;\n" :: "r"(dst), "l"(src));
}
__device__ __forceinline__ void mma_tf32(float* d, const uint32_t* a, const uint32_t* b) {
    asm volatile(
        "mma.sync.aligned.m16n8k8.row.col.f32.tf32.tf32.f32 "
        "{%0,%1,%2,%3}, {%4,%5,%6,%7}, {%8,%9}, {%0,%1,%2,%3};\n"
        : "+f"(d[0]), "+f"(d[1]), "+f"(d[2]), "+f"(d[3])
        : "r"(a[0]), "r"(a[1]), "r"(a[2]), "r"(a[3]),
          "r"(b[0]), "r"(b[1]));
}

__global__ __launch_bounds__(256) void gemm_tf32(
    const float* __restrict__ A, const float* __restrict__ W,
    const float* __restrict__ bias, const float* __restrict__ resid,
    float* __restrict__ C, int K, int N, int dogelu)
{
    __shared__ float As[2][128 * APAD];
    __shared__ float Bs[2][16 * BPAD];

    const int tid  = threadIdx.x;
    const int lane = tid & 31;
    const int warp = tid >> 5;
    const int wm = (warp & 1) * 64;     // warp M offset within tile
    const int wn = (warp >> 1) * 32;    // warp N offset within tile
    const int gid = lane >> 2;          // groupID
    const int tig = lane & 3;           // thread in group

    const int m0 = blockIdx.y * 128, n0 = blockIdx.x * 128;

    // cp.async fill mappings: 512 16B-chunks per stage for each of A and B
    const int a_row0 = tid >> 1,        a_c4 = (tid & 1) * 4;      // chunks 0..255
    const int a_row1 = (tid + 256) >> 1;                            // chunks 256..511 (c4+8? no)
    // chunk ch: row = ch>>2, c4 = (ch&3)*4. Do it generically below instead.

    float acc[4][4][4];
    #pragma unroll
    for (int mt = 0; mt < 4; mt++)
        #pragma unroll
        for (int nt = 0; nt < 4; nt++)
            #pragma unroll
            for (int e = 0; e < 4; e++) acc[mt][nt][e] = 0.f;

    uint32_t asbase = (uint32_t)__cvta_generic_to_shared(&As[0][0]);
    uint32_t bsbase = (uint32_t)__cvta_generic_to_shared(&Bs[0][0]);

    const int KT = K >> 4;

    // --- prefetch helper (inlined twice) ---
    #define PREFETCH(stg, kk0)                                                      \
    {                                                                               \
        int ch0 = tid, ch1 = tid + 256;                                             \
        {   int r = ch0 >> 2, c4 = (ch0 & 3) * 4;                                   \
            cp16(asbase + ((stg) * 128 * APAD + r * APAD + c4) * 4,                 \
                 A + (long long)(m0 + r) * K + (kk0) + c4); }                        \
        {   int r = ch1 >> 2, c4 = (ch1 & 3) * 4;                                   \
            cp16(asbase + ((stg) * 128 * APAD + r * APAD + c4) * 4,                 \
                 A + (long long)(m0 + r) * K + (kk0) + c4); }                        \
        {   int r = ch0 >> 5, c4 = (ch0 & 31) * 4;                                  \
            cp16(bsbase + ((stg) * 16 * BPAD + r * BPAD + c4) * 4,                  \
                 W + (long long)((kk0) + r) * N + n0 + c4); }                        \
        {   int r = ch1 >> 5, c4 = (ch1 & 31) * 4;                                  \
            cp16(bsbase + ((stg) * 16 * BPAD + r * BPAD + c4) * 4,                  \
                 W + (long long)((kk0) + r) * N + n0 + c4); }                        \
    }

    PREFETCH(0, 0);
    asm volatile("cp.async.commit_group;\n");

    for (int kt = 0; kt < KT; kt++) {
        int cur = kt & 1;
        if (kt + 1 < KT) { PREFETCH((kt + 1) & 1, (kt + 1) * 16); }
        asm volatile("cp.async.commit_group;\n");
        asm volatile("cp.async.wait_group 1;\n");
        __syncthreads();

        const float* as = &As[cur][0];
        const float* bs = &Bs[cur][0];
        #pragma unroll
        for (int kk = 0; kk < 2; kk++) {
            int kb = kk * 8;
            // B fragments: 4 n-tiles x 2 regs
            uint32_t bf[4][2];
            #pragma unroll
            for (int nt = 0; nt < 4; nt++) {
                int n = wn + nt * 8 + gid;
                bf[nt][0] = f2tf32(bs[(kb + tig) * BPAD + n]);
                bf[nt][1] = f2tf32(bs[(kb + 4 + tig) * BPAD + n]);
            }
            // A fragments: 4 m-tiles x 4 regs
            uint32_t af[4][4];
            #pragma unroll
            for (int mt = 0; mt < 4; mt++) {
                int r = wm + mt * 16 + gid;
                af[mt][0] = f2tf32(as[r * APAD + kb + tig]);
                af[mt][1] = f2tf32(as[(r + 8) * APAD + kb + tig]);
                af[mt][2] = f2tf32(as[r * APAD + kb + 4 + tig]);
                af[mt][3] = f2tf32(as[(r + 8) * APAD + kb + 4 + tig]);
            }
            #pragma unroll
            for (int mt = 0; mt < 4; mt++)
                #pragma unroll
                for (int nt = 0; nt < 4; nt++)
                    mma_tf32(acc[mt][nt], af[mt], bf[nt]);
        }
        __syncthreads();
    }

    // Epilogue: bias (+gelu) (+residual), direct float2 stores
    #pragma unroll
    for (int mt = 0; mt < 4; mt++) {
        #pragma unroll
        for (int nt = 0; nt < 4; nt++) {
            int c = n0 + wn + nt * 8 + 2 * tig;
            float2 bv = *(const float2*)(bias + c);
            #pragma unroll
            for (int half = 0; half < 2; half++) {
                long long r = m0 + wm + mt * 16 + gid + half * 8;
                float2 v;
                v.x = acc[mt][nt][2 * half + 0] + bv.x;
                v.y = acc[mt][nt][2 * half + 1] + bv.y;
                if (dogelu) { v.x = gelu_exact(v.x); v.y = gelu_exact(v.y); }
                if (resid) {
                    float2 rv = *(const float2*)(resid + r * N + c);
                    v.x += rv.x; v.y += rv.y;
                }
                *(float2*)(C + r * N + c) = v;
            }
        }
    }
}

// ---------------------------------------------------------------------------
// Flash attention: block = (b,h) x 64-query tile; BK = 64 keys per step.
// 256 threads, 4x4 micro-tiles, online softmax. Static smem = exactly 48KB.
// KsT buffer is reused as the P (probabilities) buffer between sub-GEMMs.
// ---------------------------------------------------------------------------
__global__ __launch_bounds__(256) void attn_kernel(
    const float* __restrict__ Qp, int ldq, long long qbs,
    const float* __restrict__ Kp, int ldk, long long kbs,
    const float* __restrict__ Vp, int ldv, long long vbs,
    float* __restrict__ Op, int ldo, long long obs,
    const int* __restrict__ maskp, int Mk, int causal)
{
    __shared__ float Qs [64 * 64];   // [q][d]
    __shared__ float KsT[64 * 64];   // [d][key] xor-swizzled; reused as P[q][key]
    __shared__ float Vs [64 * 64];   // [key][d]

    int tid = threadIdx.x;
    int tx = tid & 15, ty = tid >> 4;
    int b = blockIdx.x >> 4, h = blockIdx.x & 15;
    int q0 = blockIdx.y * 64;

    const float* Q  = Qp + b * qbs + h * 64;
    const float* Kb = Kp + b * kbs + h * 64;
    const float* Vb = Vp + b * vbs + h * 64;
    const int*   mk = maskp ? (maskp + (long long)b * Mk) : (const int*)0;

    // Load Q tile (64 rows x 64 d)
    #pragma unroll
    for (int p = 0; p < 4; p++) {
        int idx = tid + 256 * p;
        int r = idx >> 4, c4 = (idx & 15) * 4;
        float4 qv = *(const float4*)(Q + (long long)(q0 + r) * ldq + c4);
        *(float4*)&Qs[r * 64 + c4] = qv;
    }

    float m_i[4], l_i[4], acc[4][4];
    #pragma unroll
    for (int i = 0; i < 4; i++) {
        m_i[i] = -1e30f; l_i[i] = 0.f;
        #pragma unroll
        for (int j = 0; j < 4; j++) acc[i][j] = 0.f;
    }

    int nkt = causal ? (blockIdx.y + 1) : (Mk / 64);
    for (int kt = 0; kt < nkt; kt++) {
        int k0 = kt * 64;
        __syncthreads();   // prior GEMM2 reads done (and Q load on iter 0)

        // Fill KsT (xor-swizzled transpose) and Vs (row-major), coalesced
        #pragma unroll
        for (int p = 0; p < 4; p++) {
            int idx = tid + 256 * p;
            int key = idx >> 4, c4 = (idx & 15) * 4;
            float4 kv = *(const float4*)(Kb + (long long)(k0 + key) * ldk + c4);
            float kvarr[4] = {kv.x, kv.y, kv.z, kv.w};
            #pragma unroll
            for (int e = 0; e < 4; e++) {
                int d = c4 + e;
                KsT[d * 64 + (((key >> 2) ^ (d & 15)) << 2) + (key & 3)] = kvarr[e];
            }
            float4 vv = *(const float4*)(Vb + (long long)(k0 + key) * ldv + c4);
            *(float4*)&Vs[key * 64 + c4] = vv;
        }
        __syncthreads();

        // GEMM1: S = Q @ K^T for this 64x64 tile
        float s[4][4];
        #pragma unroll
        for (int i = 0; i < 4; i++)
            #pragma unroll
            for (int j = 0; j < 4; j++) s[i][j] = 0.f;
        #pragma unroll 16
        for (int d = 0; d < 64; d++) {
            float4 k4 = *(const float4*)&KsT[d * 64 + ((tx ^ (d & 15)) << 2)];
            float a0 = Qs[(4 * ty + 0) * 64 + d];
            float a1 = Qs[(4 * ty + 1) * 64 + d];
            float a2 = Qs[(4 * ty + 2) * 64 + d];
            float a3 = Qs[(4 * ty + 3) * 64 + d];
            s[0][0] += a0 * k4.x; s[0][1] += a0 * k4.y; s[0][2] += a0 * k4.z; s[0][3] += a0 * k4.w;
            s[1][0] += a1 * k4.x; s[1][1] += a1 * k4.y; s[1][2] += a1 * k4.z; s[1][3] += a1 * k4.w;
            s[2][0] += a2 * k4.x; s[2][1] += a2 * k4.y; s[2][2] += a2 * k4.z; s[2][3] += a2 * k4.w;
            s[3][0] += a3 * k4.x; s[3][1] += a3 * k4.y; s[3][2] += a3 * k4.z; s[3][3] += a3 * k4.w;
        }

        // Scale + masks
        bool diag = (causal != 0) && (k0 == q0);
        int mval[4] = {1, 1, 1, 1};
        if (mk) {
            #pragma unroll
            for (int j = 0; j < 4; j++) mval[j] = mk[k0 + 4 * tx + j];
        }
        #pragma unroll
        for (int i = 0; i < 4; i++)
            #pragma unroll
            for (int j = 0; j < 4; j++) {
                float sv = s[i][j] * 0.125f;   // 1/sqrt(64)
                if (diag && (k0 + 4 * tx + j > q0 + 4 * ty + i)) sv = NEGINF;
                if (mk && mval[j] == 0) sv = NEGINF;
                s[i][j] = sv;
            }
        __syncthreads();   // all KsT reads finished before P overwrites it

        // Online softmax update; write P into KsT buffer (plain layout)
        #pragma unroll
        for (int i = 0; i < 4; i++) {
            float rmax = fmaxf(fmaxf(s[i][0], s[i][1]), fmaxf(s[i][2], s[i][3]));
            #pragma unroll
            for (int o = 1; o < 16; o <<= 1)
                rmax = fmaxf(rmax, __shfl_xor_sync(0xffffffffu, rmax, o));
            float mnew = fmaxf(m_i[i], rmax);
            float sc = __expf(m_i[i] - mnew);
            float p0 = __expf(s[i][0] - mnew);
            float p1 = __expf(s[i][1] - mnew);
            float p2 = __expf(s[i][2] - mnew);
            float p3 = __expf(s[i][3] - mnew);
            float rsum = p0 + p1 + p2 + p3;
            #pragma unroll
            for (int o = 1; o < 16; o <<= 1)
                rsum += __shfl_xor_sync(0xffffffffu, rsum, o);
            l_i[i] = l_i[i] * sc + rsum;
            m_i[i] = mnew;
            acc[i][0] *= sc; acc[i][1] *= sc; acc[i][2] *= sc; acc[i][3] *= sc;
            int r = 4 * ty + i;
            KsT[r * 64 + 4 * tx + 0] = p0;
            KsT[r * 64 + 4 * tx + 1] = p1;
            KsT[r * 64 + 4 * tx + 2] = p2;
            KsT[r * 64 + 4 * tx + 3] = p3;
        }
        __syncthreads();

        // GEMM2: O += P @ V
        #pragma unroll 16
        for (int kk = 0; kk < 64; kk++) {
            float4 v4 = *(const float4*)&Vs[kk * 64 + 4 * tx];
            float p0 = KsT[(4 * ty + 0) * 64 + kk];
            float p1 = KsT[(4 * ty + 1) * 64 + kk];
            float p2 = KsT[(4 * ty + 2) * 64 + kk];
            float p3 = KsT[(4 * ty + 3) * 64 + kk];
            acc[0][0] += p0 * v4.x; acc[0][1] += p0 * v4.y; acc[0][2] += p0 * v4.z; acc[0][3] += p0 * v4.w;
            acc[1][0] += p1 * v4.x; acc[1][1] += p1 * v4.y; acc[1][2] += p1 * v4.z; acc[1][3] += p1 * v4.w;
            acc[2][0] += p2 * v4.x; acc[2][1] += p2 * v4.y; acc[2][2] += p2 * v4.z; acc[2][3] += p2 * v4.w;
            acc[3][0] += p3 * v4.x; acc[3][1] += p3 * v4.y; acc[3][2] += p3 * v4.z; acc[3][3] += p3 * v4.w;
        }
    }

    // Normalize and write output
    #pragma unroll
    for (int i = 0; i < 4; i++) {
        float inv = 1.0f / l_i[i];
        float4 o;
        o.x = acc[i][0] * inv; o.y = acc[i][1] * inv;
        o.z = acc[i][2] * inv; o.w = acc[i][3] * inv;
        *(float4*)(Op + b * obs + (long long)(q0 + 4 * ty + i) * ldo + h * 64 + 4 * tx) = o;
    }
}

// ---------------------------------------------------------------------------
// Launch: 12 graph-capturable kernel launches on the default stream
// ---------------------------------------------------------------------------
extern "C" void kernel_launch(void* const* d_in, const int* in_sizes, int n_in,
                              void* d_out, int out_size)
{
    const float* x         = (const float*)d_in[0];
    const float* mem       = (const float*)d_in[1];
    const int*   mem_mask  = (const int*)  d_in[2];
    const float* ln1_w     = (const float*)d_in[3];
    const float* ln1_b     = (const float*)d_in[4];
    const float* sa_qkv_w  = (const float*)d_in[5];
    const float* sa_qkv_b  = (const float*)d_in[6];
    const float* sa_proj_w = (const float*)d_in[7];
    const float* sa_proj_b = (const float*)d_in[8];
    const float* lnm_w     = (const float*)d_in[9];
    const float* lnm_b     = (const float*)d_in[10];
    const float* ca_q_w    = (const float*)d_in[11];
    const float* ca_q_b    = (const float*)d_in[12];
    const float* ca_kv_w   = (const float*)d_in[13];
    const float* ca_kv_b   = (const float*)d_in[14];
    const float* ca_proj_w = (const float*)d_in[15];
    const float* ca_proj_b = (const float*)d_in[16];
    const float* ln2_w     = (const float*)d_in[17];
    const float* ln2_b     = (const float*)d_in[18];
    const float* ff1_w     = (const float*)d_in[19];
    const float* ff1_b     = (const float*)d_in[20];
    const float* ff2_w     = (const float*)d_in[21];
    const float* ff2_b     = (const float*)d_in[22];
    float* out = (float*)d_out;

    float *h, *qkv, *y, *xr, *kv, *ff;
    cudaGetSymbolAddress((void**)&h,   g_h);
    cudaGetSymbolAddress((void**)&qkv, g_qkv);
    cudaGetSymbolAddress((void**)&y,   g_y);
    cudaGetSymbolAddress((void**)&xr,  g_x);
    cudaGetSymbolAddress((void**)&kv,  g_kv);
    cudaGetSymbolAddress((void**)&ff,  g_ff);

    // 1) h = LN(x)
    ln_kernel<<<NX, 256>>>(x, ln1_w, ln1_b, h);
    // 2) qkv = h @ Wqkv + b
    gemm_tf32<<<dim3(3 * Dx / 128, NX / 128), 256>>>(h, sa_qkv_w, sa_qkv_b, 0, qkv, Dx, 3 * Dx, 0);
    // 3) y = causal self-attention(qkv)
    attn_kernel<<<dim3(Bx * Hx, Tx / 64), 256>>>(
        qkv,            3 * Dx, (long long)Tx * 3 * Dx,
        qkv + Dx,       3 * Dx, (long long)Tx * 3 * Dx,
        qkv + 2 * Dx,   3 * Dx, (long long)Tx * 3 * Dx,
        y,              Dx,     (long long)Tx * Dx,
        (const int*)0, Tx, 1);
    // 4) x1 = x + y @ Wproj + b
    gemm_tf32<<<dim3(Dx / 128, NX / 128), 256>>>(y, sa_proj_w, sa_proj_b, x, xr, Dx, Dx, 0);
    // 5) h = LN(x1)
    ln_kernel<<<NX, 256>>>(xr, lnm_w, lnm_b, h);
    // 6) qc = h @ Wq + b   (into g_y)
    gemm_tf32<<<dim3(Dx / 128, NX / 128), 256>>>(h, ca_q_w, ca_q_b, 0, y, Dx, Dx, 0);
    // 7) kv = mem @ Wkv + b
    gemm_tf32<<<dim3(2 * Dx / 128, NM / 128), 256>>>(mem, ca_kv_w, ca_kv_b, 0, kv, Dx, 2 * Dx, 0);
    // 8) yc = cross-attention(qc, kv, mem_mask)  (into g_h)
    attn_kernel<<<dim3(Bx * Hx, Tx / 64), 256>>>(
        y,         Dx,     (long long)Tx * Dx,
        kv,        2 * Dx, (long long)Mx * 2 * Dx,
        kv + Dx,   2 * Dx, (long long)Mx * 2 * Dx,
        h,         Dx,     (long long)Tx * Dx,
        mem_mask, Mx, 0);
    // 9) x2 = x1 + yc @ Wcp + b  (in-place residual)
    gemm_tf32<<<dim3(Dx / 128, NX / 128), 256>>>(h, ca_proj_w, ca_proj_b, xr, xr, Dx, Dx, 0);
    // 10) h = LN(x2)
    ln_kernel<<<NX, 256>>>(xr, ln2_w, ln2_b, h);
    // 11) ff = gelu(h @ W1 + b)
    gemm_tf32<<<dim3(DFFx / 128, NX / 128), 256>>>(h, ff1_w, ff1_b, 0, ff, Dx, DFFx, 1);
    // 12) out = x2 + ff @ W2 + b
    gemm_tf32<<<dim3(Dx / 128, NX / 128), 256>>>(ff, ff2_w, ff2_b, xr, out, DFFx, Dx, 0);
}

// round 3
// speedup vs baseline: 2.0155x; 1.0380x over previous
#include <cuda_runtime.h>
#include <math.h>
#include <stdint.h>

// Problem dims (fixed by the reference)
#define Bx   4
#define Tx   2048
#define Mx   2048
#define Dx   1024
#define Hx   16
#define DKx  64
#define DFFx 4096
#define NX   (Bx*Tx)   // 8192 rows of x
#define NM   (Bx*Mx)   // 8192 rows of mem

#define NEGINF (__int_as_float(0xff800000))

// ---------------------------------------------------------------------------
// Scratch (device globals; allocation-free per harness rules)
// ---------------------------------------------------------------------------
__device__ float g_h  [NX * Dx];        // LN outputs / yc (tf32-rounded)
__device__ float g_qkv[NX * 3 * Dx];    // self-attn qkv (fp32)
__device__ float g_y  [NX * Dx];        // attn out / qc (tf32-rounded where needed)
__device__ float g_x  [NX * Dx];        // running residual (fp32)
__device__ float g_kv [NM * 2 * Dx];    // cross kv (fp32)
__device__ float g_ff [NX * DFFx];      // ffn hidden (tf32-rounded)
__device__ float g_w  [16 * 1024 * 1024]; // tf32-rounded weights (concatenated)
__device__ float g_memt[NM * Dx];       // tf32-rounded mem

// Offsets into g_w (floats)
#define WOFF_QKV    0                       // 3M
#define WOFF_PROJ   (3*1024*1024)           // 1M
#define WOFF_CAQ    (4*1024*1024)           // 1M
#define WOFF_CAKV   (5*1024*1024)           // 2M
#define WOFF_CAPROJ (7*1024*1024)           // 1M
#define WOFF_FF1    (8*1024*1024)           // 4M
#define WOFF_FF2    (12*1024*1024)          // 4M

__device__ __forceinline__ uint32_t f2tf32(float f) {
    uint32_t r;
    asm("cvt.rna.tf32.f32 %0, %1;\n" : "=r"(r) : "f"(f));
    return r;
}
__device__ __forceinline__ float rtf32(float f) {
    return __uint_as_float(f2tf32(f));
}

// ---------------------------------------------------------------------------
// Bulk fp32 -> tf32-bit-pattern conversion (vectorized), n % 1024 == 0
// ---------------------------------------------------------------------------
__global__ __launch_bounds__(256) void cvt_tf32_kernel(
    const float* __restrict__ src, float* __restrict__ dst)
{
    long long i = ((long long)blockIdx.x * 256 + threadIdx.x) * 4;
    float4 v = *(const float4*)(src + i);
    v.x = rtf32(v.x); v.y = rtf32(v.y); v.z = rtf32(v.z); v.w = rtf32(v.w);
    *(float4*)(dst + i) = v;
}

// ---------------------------------------------------------------------------
// LayerNorm: one block per row, D = 1024, 256 threads (one float4 each)
// Output is tf32-rounded (it only ever feeds tensor-core GEMM A operands).
// ---------------------------------------------------------------------------
__global__ __launch_bounds__(256) void ln_kernel(
    const float* __restrict__ X, const float* __restrict__ w,
    const float* __restrict__ b, float* __restrict__ out)
{
    long long row = blockIdx.x;
    const float* xr = X + row * Dx;
    int t = threadIdx.x;
    float4 v = *(const float4*)(xr + t * 4);
    float s  = v.x + v.y + v.z + v.w;
    float ss = v.x*v.x + v.y*v.y + v.z*v.z + v.w*v.w;
    #pragma unroll
    for (int o = 16; o > 0; o >>= 1) {
        s  += __shfl_xor_sync(0xffffffffu, s, o);
        ss += __shfl_xor_sync(0xffffffffu, ss, o);
    }
    __shared__ float rs[8], rss[8];
    __shared__ float smu, srstd;
    if ((t & 31) == 0) { rs[t >> 5] = s; rss[t >> 5] = ss; }
    __syncthreads();
    if (t == 0) {
        float S = 0.f, SS = 0.f;
        #pragma unroll
        for (int i = 0; i < 8; i++) { S += rs[i]; SS += rss[i]; }
        float mu  = S * (1.0f / Dx);
        float var = SS * (1.0f / Dx) - mu * mu;
        smu = mu; srstd = rsqrtf(var + 1e-5f);
    }
    __syncthreads();
    float mu = smu, r = srstd;
    float4 wv = *(const float4*)(w + t * 4);
    float4 bv = *(const float4*)(b + t * 4);
    float4 o;
    o.x = rtf32((v.x - mu) * r * wv.x + bv.x);
    o.y = rtf32((v.y - mu) * r * wv.y + bv.y);
    o.z = rtf32((v.z - mu) * r * wv.z + bv.z);
    o.w = rtf32((v.w - mu) * r * wv.w + bv.w);
    *(float4*)(out + row * Dx + t * 4) = o;
}

// ---------------------------------------------------------------------------
// TF32 tensor-core GEMM: C[M,N] = A[M,K] @ W[K,N] + bias (+gelu) (+residual)
// A and W MUST already be tf32-rounded bit patterns. No cvt in mainloop.
// 128x128 tile, BK=16, 256 threads (2x4 warp grid, 64x32 warp tiles),
// mma.sync.m16n8k8.tf32, cp.async double buffering. Static smem = 37.9KB.
// ---------------------------------------------------------------------------
#define APAD 20     // A smem row stride (floats): conflict-free fragment LDS
#define BPAD 136    // B smem row stride (floats): conflict-free fragment LDS

__device__ __forceinline__ float gelu_exact(float v) {
    return 0.5f * v * (1.0f + erff(v * 0.7071067811865476f));
}
__device__ __forceinline__ void cp16(uint32_t dst, const void* src) {
    asm volatile("cp.async.cg.shared.global [%0], [%1], 16;\n" :: "r"(dst), "l"(src));
}
__device__ __forceinline__ void mma_tf32(float* d, const uint32_t* a, const uint32_t* b) {
    asm volatile(
        "mma.sync.aligned.m16n8k8.row.col.f32.tf32.tf32.f32 "
        "{%0,%1,%2,%3}, {%4,%5,%6,%7}, {%8,%9}, {%0,%1,%2,%3};\n"
        : "+f"(d[0]), "+f"(d[1]), "+f"(d[2]), "+f"(d[3])
        : "r"(a[0]), "r"(a[1]), "r"(a[2]), "r"(a[3]),
          "r"(b[0]), "r"(b[1]));
}

__global__ __launch_bounds__(256) void gemm_tf32(
    const float* __restrict__ A, const float* __restrict__ W,
    const float* __restrict__ bias, const float* __restrict__ resid,
    float* __restrict__ C, int K, int N, int dogelu, int roundout)
{
    __shared__ float As[2][128 * APAD];
    __shared__ float Bs[2][16 * BPAD];

    const int tid  = threadIdx.x;
    const int lane = tid & 31;
    const int warp = tid >> 5;
    const int wm = (warp & 1) * 64;     // warp M offset within tile
    const int wn = (warp >> 1) * 32;    // warp N offset within tile
    const int gid = lane >> 2;          // groupID
    const int tig = lane & 3;           // thread in group

    const int m0 = blockIdx.y * 128, n0 = blockIdx.x * 128;

    float acc[4][4][4];
    #pragma unroll
    for (int mt = 0; mt < 4; mt++)
        #pragma unroll
        for (int nt = 0; nt < 4; nt++)
            #pragma unroll
            for (int e = 0; e < 4; e++) acc[mt][nt][e] = 0.f;

    uint32_t asbase = (uint32_t)__cvta_generic_to_shared(&As[0][0]);
    uint32_t bsbase = (uint32_t)__cvta_generic_to_shared(&Bs[0][0]);

    const int KT = K >> 4;

    #define PREFETCH(stg, kk0)                                                      \
    {                                                                               \
        int ch0 = tid, ch1 = tid + 256;                                             \
        {   int r = ch0 >> 2, c4 = (ch0 & 3) * 4;                                   \
            cp16(asbase + ((stg) * 128 * APAD + r * APAD + c4) * 4,                 \
                 A + (long long)(m0 + r) * K + (kk0) + c4); }                        \
        {   int r = ch1 >> 2, c4 = (ch1 & 3) * 4;                                   \
            cp16(asbase + ((stg) * 128 * APAD + r * APAD + c4) * 4,                 \
                 A + (long long)(m0 + r) * K + (kk0) + c4); }                        \
        {   int r = ch0 >> 5, c4 = (ch0 & 31) * 4;                                  \
            cp16(bsbase + ((stg) * 16 * BPAD + r * BPAD + c4) * 4,                  \
                 W + (long long)((kk0) + r) * N + n0 + c4); }                        \
        {   int r = ch1 >> 5, c4 = (ch1 & 31) * 4;                                  \
            cp16(bsbase + ((stg) * 16 * BPAD + r * BPAD + c4) * 4,                  \
                 W + (long long)((kk0) + r) * N + n0 + c4); }                        \
    }

    PREFETCH(0, 0);
    asm volatile("cp.async.commit_group;\n");

    for (int kt = 0; kt < KT; kt++) {
        int cur = kt & 1;
        if (kt + 1 < KT) { PREFETCH((kt + 1) & 1, (kt + 1) * 16); }
        asm volatile("cp.async.commit_group;\n");
        asm volatile("cp.async.wait_group 1;\n");
        __syncthreads();

        const uint32_t* as = (const uint32_t*)&As[cur][0];
        const uint32_t* bs = (const uint32_t*)&Bs[cur][0];
        #pragma unroll
        for (int kk = 0; kk < 2; kk++) {
            int kb = kk * 8;
            // B fragments: 4 n-tiles x 2 regs (raw tf32 bits, no cvt)
            uint32_t bf[4][2];
            #pragma unroll
            for (int nt = 0; nt < 4; nt++) {
                int n = wn + nt * 8 + gid;
                bf[nt][0] = bs[(kb + tig) * BPAD + n];
                bf[nt][1] = bs[(kb + 4 + tig) * BPAD + n];
            }
            // A fragments: 4 m-tiles x 4 regs (raw tf32 bits, no cvt)
            uint32_t af[4][4];
            #pragma unroll
            for (int mt = 0; mt < 4; mt++) {
                int r = wm + mt * 16 + gid;
                af[mt][0] = as[r * APAD + kb + tig];
                af[mt][1] = as[(r + 8) * APAD + kb + tig];
                af[mt][2] = as[r * APAD + kb + 4 + tig];
                af[mt][3] = as[(r + 8) * APAD + kb + 4 + tig];
            }
            #pragma unroll
            for (int mt = 0; mt < 4; mt++)
                #pragma unroll
                for (int nt = 0; nt < 4; nt++)
                    mma_tf32(acc[mt][nt], af[mt], bf[nt]);
        }
        __syncthreads();
    }

    // Epilogue: bias (+gelu) (+residual) (+tf32 rounding), float2 stores
    #pragma unroll
    for (int mt = 0; mt < 4; mt++) {
        #pragma unroll
        for (int nt = 0; nt < 4; nt++) {
            int c = n0 + wn + nt * 8 + 2 * tig;
            float2 bv = *(const float2*)(bias + c);
            #pragma unroll
            for (int half = 0; half < 2; half++) {
                long long r = m0 + wm + mt * 16 + gid + half * 8;
                float2 v;
                v.x = acc[mt][nt][2 * half + 0] + bv.x;
                v.y = acc[mt][nt][2 * half + 1] + bv.y;
                if (dogelu) { v.x = gelu_exact(v.x); v.y = gelu_exact(v.y); }
                if (resid) {
                    float2 rv = *(const float2*)(resid + r * N + c);
                    v.x += rv.x; v.y += rv.y;
                }
                if (roundout) { v.x = rtf32(v.x); v.y = rtf32(v.y); }
                *(float2*)(C + r * N + c) = v;
            }
        }
    }
}

// ---------------------------------------------------------------------------
// Flash attention: block = (b,h) x 64-query tile; BK = 64 keys per step.
// 256 threads, 4x4 micro-tiles, online softmax. Static smem = exactly 48KB.
// Output is tf32-rounded (it only feeds GEMM A operands).
// ---------------------------------------------------------------------------
__global__ __launch_bounds__(256) void attn_kernel(
    const float* __restrict__ Qp, int ldq, long long qbs,
    const float* __restrict__ Kp, int ldk, long long kbs,
    const float* __restrict__ Vp, int ldv, long long vbs,
    float* __restrict__ Op, int ldo, long long obs,
    const int* __restrict__ maskp, int Mk, int causal)
{
    __shared__ float Qs [64 * 64];   // [q][d]
    __shared__ float KsT[64 * 64];   // [d][key] xor-swizzled; reused as P[q][key]
    __shared__ float Vs [64 * 64];   // [key][d]

    int tid = threadIdx.x;
    int tx = tid & 15, ty = tid >> 4;
    int b = blockIdx.x >> 4, h = blockIdx.x & 15;
    int q0 = blockIdx.y * 64;

    const float* Q  = Qp + b * qbs + h * 64;
    const float* Kb = Kp + b * kbs + h * 64;
    const float* Vb = Vp + b * vbs + h * 64;
    const int*   mk = maskp ? (maskp + (long long)b * Mk) : (const int*)0;

    // Load Q tile (64 rows x 64 d)
    #pragma unroll
    for (int p = 0; p < 4; p++) {
        int idx = tid + 256 * p;
        int r = idx >> 4, c4 = (idx & 15) * 4;
        float4 qv = *(const float4*)(Q + (long long)(q0 + r) * ldq + c4);
        *(float4*)&Qs[r * 64 + c4] = qv;
    }

    float m_i[4], l_i[4], acc[4][4];
    #pragma unroll
    for (int i = 0; i < 4; i++) {
        m_i[i] = -1e30f; l_i[i] = 0.f;
        #pragma unroll
        for (int j = 0; j < 4; j++) acc[i][j] = 0.f;
    }

    int nkt = causal ? (blockIdx.y + 1) : (Mk / 64);
    for (int kt = 0; kt < nkt; kt++) {
        int k0 = kt * 64;
        __syncthreads();   // prior GEMM2 reads done (and Q load on iter 0)

        // Fill KsT (xor-swizzled transpose) and Vs (row-major), coalesced
        #pragma unroll
        for (int p = 0; p < 4; p++) {
            int idx = tid + 256 * p;
            int key = idx >> 4, c4 = (idx & 15) * 4;
            float4 kv = *(const float4*)(Kb + (long long)(k0 + key) * ldk + c4);
            float kvarr[4] = {kv.x, kv.y, kv.z, kv.w};
            #pragma unroll
            for (int e = 0; e < 4; e++) {
                int d = c4 + e;
                KsT[d * 64 + (((key >> 2) ^ (d & 15)) << 2) + (key & 3)] = kvarr[e];
            }
            float4 vv = *(const float4*)(Vb + (long long)(k0 + key) * ldv + c4);
            *(float4*)&Vs[key * 64 + c4] = vv;
        }
        __syncthreads();

        // GEMM1: S = Q @ K^T for this 64x64 tile
        float s[4][4];
        #pragma unroll
        for (int i = 0; i < 4; i++)
            #pragma unroll
            for (int j = 0; j < 4; j++) s[i][j] = 0.f;
        #pragma unroll 16
        for (int d = 0; d < 64; d++) {
            float4 k4 = *(const float4*)&KsT[d * 64 + ((tx ^ (d & 15)) << 2)];
            float a0 = Qs[(4 * ty + 0) * 64 + d];
            float a1 = Qs[(4 * ty + 1) * 64 + d];
            float a2 = Qs[(4 * ty + 2) * 64 + d];
            float a3 = Qs[(4 * ty + 3) * 64 + d];
            s[0][0] += a0 * k4.x; s[0][1] += a0 * k4.y; s[0][2] += a0 * k4.z; s[0][3] += a0 * k4.w;
            s[1][0] += a1 * k4.x; s[1][1] += a1 * k4.y; s[1][2] += a1 * k4.z; s[1][3] += a1 * k4.w;
            s[2][0] += a2 * k4.x; s[2][1] += a2 * k4.y; s[2][2] += a2 * k4.z; s[2][3] += a2 * k4.w;
            s[3][0] += a3 * k4.x; s[3][1] += a3 * k4.y; s[3][2] += a3 * k4.z; s[3][3] += a3 * k4.w;
        }

        // Scale + masks
        bool diag = (causal != 0) && (k0 == q0);
        int mval[4] = {1, 1, 1, 1};
        if (mk) {
            #pragma unroll
            for (int j = 0; j < 4; j++) mval[j] = mk[k0 + 4 * tx + j];
        }
        #pragma unroll
        for (int i = 0; i < 4; i++)
            #pragma unroll
            for (int j = 0; j < 4; j++) {
                float sv = s[i][j] * 0.125f;   // 1/sqrt(64)
                if (diag && (k0 + 4 * tx + j > q0 + 4 * ty + i)) sv = NEGINF;
                if (mk && mval[j] == 0) sv = NEGINF;
                s[i][j] = sv;
            }
        __syncthreads();   // all KsT reads finished before P overwrites it

        // Online softmax update; write P into KsT buffer (plain layout)
        #pragma unroll
        for (int i = 0; i < 4; i++) {
            float rmax = fmaxf(fmaxf(s[i][0], s[i][1]), fmaxf(s[i][2], s[i][3]));
            #pragma unroll
            for (int o = 1; o < 16; o <<= 1)
                rmax = fmaxf(rmax, __shfl_xor_sync(0xffffffffu, rmax, o));
            float mnew = fmaxf(m_i[i], rmax);
            float sc = __expf(m_i[i] - mnew);
            float p0 = __expf(s[i][0] - mnew);
            float p1 = __expf(s[i][1] - mnew);
            float p2 = __expf(s[i][2] - mnew);
            float p3 = __expf(s[i][3] - mnew);
            float rsum = p0 + p1 + p2 + p3;
            #pragma unroll
            for (int o = 1; o < 16; o <<= 1)
                rsum += __shfl_xor_sync(0xffffffffu, rsum, o);
            l_i[i] = l_i[i] * sc + rsum;
            m_i[i] = mnew;
            acc[i][0] *= sc; acc[i][1] *= sc; acc[i][2] *= sc; acc[i][3] *= sc;
            int r = 4 * ty + i;
            KsT[r * 64 + 4 * tx + 0] = p0;
            KsT[r * 64 + 4 * tx + 1] = p1;
            KsT[r * 64 + 4 * tx + 2] = p2;
            KsT[r * 64 + 4 * tx + 3] = p3;
        }
        __syncthreads();

        // GEMM2: O += P @ V
        #pragma unroll 16
        for (int kk = 0; kk < 64; kk++) {
            float4 v4 = *(const float4*)&Vs[kk * 64 + 4 * tx];
            float p0 = KsT[(4 * ty + 0) * 64 + kk];
            float p1 = KsT[(4 * ty + 1) * 64 + kk];
            float p2 = KsT[(4 * ty + 2) * 64 + kk];
            float p3 = KsT[(4 * ty + 3) * 64 + kk];
            acc[0][0] += p0 * v4.x; acc[0][1] += p0 * v4.y; acc[0][2] += p0 * v4.z; acc[0][3] += p0 * v4.w;
            acc[1][0] += p1 * v4.x; acc[1][1] += p1 * v4.y; acc[1][2] += p1 * v4.z; acc[1][3] += p1 * v4.w;
            acc[2][0] += p2 * v4.x; acc[2][1] += p2 * v4.y; acc[2][2] += p2 * v4.z; acc[2][3] += p2 * v4.w;
            acc[3][0] += p3 * v4.x; acc[3][1] += p3 * v4.y; acc[3][2] += p3 * v4.z; acc[3][3] += p3 * v4.w;
        }
    }

    // Normalize and write output (tf32-rounded: feeds GEMM A only)
    #pragma unroll
    for (int i = 0; i < 4; i++) {
        float inv = 1.0f / l_i[i];
        float4 o;
        o.x = rtf32(acc[i][0] * inv); o.y = rtf32(acc[i][1] * inv);
        o.z = rtf32(acc[i][2] * inv); o.w = rtf32(acc[i][3] * inv);
        *(float4*)(Op + b * obs + (long long)(q0 + 4 * ty + i) * ldo + h * 64 + 4 * tx) = o;
    }
}

// ---------------------------------------------------------------------------
// Launch: graph-capturable kernel launches on the default stream
// ---------------------------------------------------------------------------
extern "C" void kernel_launch(void* const* d_in, const int* in_sizes, int n_in,
                              void* d_out, int out_size)
{
    const float* x         = (const float*)d_in[0];
    const float* mem       = (const float*)d_in[1];
    const int*   mem_mask  = (const int*)  d_in[2];
    const float* ln1_w     = (const float*)d_in[3];
    const float* ln1_b     = (const float*)d_in[4];
    const float* sa_qkv_w  = (const float*)d_in[5];
    const float* sa_qkv_b  = (const float*)d_in[6];
    const float* sa_proj_w = (const float*)d_in[7];
    const float* sa_proj_b = (const float*)d_in[8];
    const float* lnm_w     = (const float*)d_in[9];
    const float* lnm_b     = (const float*)d_in[10];
    const float* ca_q_w    = (const float*)d_in[11];
    const float* ca_q_b    = (const float*)d_in[12];
    const float* ca_kv_w   = (const float*)d_in[13];
    const float* ca_kv_b   = (const float*)d_in[14];
    const float* ca_proj_w = (const float*)d_in[15];
    const float* ca_proj_b = (const float*)d_in[16];
    const float* ln2_w     = (const float*)d_in[17];
    const float* ln2_b     = (const float*)d_in[18];
    const float* ff1_w     = (const float*)d_in[19];
    const float* ff1_b     = (const float*)d_in[20];
    const float* ff2_w     = (const float*)d_in[21];
    const float* ff2_b     = (const float*)d_in[22];
    float* out = (float*)d_out;

    float *h, *qkv, *y, *xr, *kv, *ff, *wsc, *memt;
    cudaGetSymbolAddress((void**)&h,    g_h);
    cudaGetSymbolAddress((void**)&qkv,  g_qkv);
    cudaGetSymbolAddress((void**)&y,    g_y);
    cudaGetSymbolAddress((void**)&xr,   g_x);
    cudaGetSymbolAddress((void**)&kv,   g_kv);
    cudaGetSymbolAddress((void**)&ff,   g_ff);
    cudaGetSymbolAddress((void**)&wsc,  g_w);
    cudaGetSymbolAddress((void**)&memt, g_memt);

    // 0) One-pass tf32 pre-rounding of all GEMM operands that are raw inputs
    cvt_tf32_kernel<<<3 * Dx * Dx / 1024, 256>>>(sa_qkv_w,  wsc + WOFF_QKV);
    cvt_tf32_kernel<<<Dx * Dx / 1024,     256>>>(sa_proj_w, wsc + WOFF_PROJ);
    cvt_tf32_kernel<<<Dx * Dx / 1024,     256>>>(ca_q_w,    wsc + WOFF_CAQ);
    cvt_tf32_kernel<<<2 * Dx * Dx / 1024, 256>>>(ca_kv_w,   wsc + WOFF_CAKV);
    cvt_tf32_kernel<<<Dx * Dx / 1024,     256>>>(ca_proj_w, wsc + WOFF_CAPROJ);
    cvt_tf32_kernel<<<Dx * DFFx / 1024,   256>>>(ff1_w,     wsc + WOFF_FF1);
    cvt_tf32_kernel<<<DFFx * Dx / 1024,   256>>>(ff2_w,     wsc + WOFF_FF2);
    cvt_tf32_kernel<<<NM * Dx / 1024,     256>>>(mem,       memt);

    // 1) h = LN(x)  (tf32-rounded)
    ln_kernel<<<NX, 256>>>(x, ln1_w, ln1_b, h);
    // 2) qkv = h @ Wqkv + b  (fp32 out; consumed by SIMT attention)
    gemm_tf32<<<dim3(3 * Dx / 128, NX / 128), 256>>>(h, wsc + WOFF_QKV, sa_qkv_b, 0, qkv, Dx, 3 * Dx, 0, 0);
    // 3) y = causal self-attention(qkv)  (tf32-rounded out)
    attn_kernel<<<dim3(Bx * Hx, Tx / 64), 256>>>(
        qkv,            3 * Dx, (long long)Tx * 3 * Dx,
        qkv + Dx,       3 * Dx, (long long)Tx * 3 * Dx,
        qkv + 2 * Dx,   3 * Dx, (long long)Tx * 3 * Dx,
        y,              Dx,     (long long)Tx * Dx,
        (const int*)0, Tx, 1);
    // 4) x1 = x + y @ Wproj + b  (fp32 residual)
    gemm_tf32<<<dim3(Dx / 128, NX / 128), 256>>>(y, wsc + WOFF_PROJ, sa_proj_b, x, xr, Dx, Dx, 0, 0);
    // 5) h = LN(x1)  (tf32-rounded)
    ln_kernel<<<NX, 256>>>(xr, lnm_w, lnm_b, h);
    // 6) qc = h @ Wq + b  (fp32; consumed by SIMT attention)
    gemm_tf32<<<dim3(Dx / 128, NX / 128), 256>>>(h, wsc + WOFF_CAQ, ca_q_b, 0, y, Dx, Dx, 0, 0);
    // 7) kv = mem @ Wkv + b  (fp32; consumed by SIMT attention)
    gemm_tf32<<<dim3(2 * Dx / 128, NM / 128), 256>>>(memt, wsc + WOFF_CAKV, ca_kv_b, 0, kv, Dx, 2 * Dx, 0, 0);
    // 8) yc = cross-attention(qc, kv, mem_mask)  (tf32-rounded out, into g_h)
    attn_kernel<<<dim3(Bx * Hx, Tx / 64), 256>>>(
        y,         Dx,     (long long)Tx * Dx,
        kv,        2 * Dx, (long long)Mx * 2 * Dx,
        kv + Dx,   2 * Dx, (long long)Mx * 2 * Dx,
        h,         Dx,     (long long)Tx * Dx,
        mem_mask, Mx, 0);
    // 9) x2 = x1 + yc @ Wcp + b  (fp32 residual)
    gemm_tf32<<<dim3(Dx / 128, NX / 128), 256>>>(h, wsc + WOFF_CAPROJ, ca_proj_b, xr, xr, Dx, Dx, 0, 0);
    // 10) h = LN(x2)  (tf32-rounded)
    ln_kernel<<<NX, 256>>>(xr, ln2_w, ln2_b, h);
    // 11) ff = gelu(h @ W1 + b)  (tf32-rounded out: feeds GEMM 12 as A)
    gemm_tf32<<<dim3(DFFx / 128, NX / 128), 256>>>(h, wsc + WOFF_FF1, ff1_b, 0, ff, Dx, DFFx, 1, 1);
    // 12) out = x2 + ff @ W2 + b  (fp32 final)
    gemm_tf32<<<dim3(Dx / 128, NX / 128), 256>>>(ff, wsc + WOFF_FF2, ff2_b, xr, out, DFFx, Dx, 0, 0);
}

// round 4
// speedup vs baseline: 2.6780x; 1.3287x over previous
#include <cuda_runtime.h>
#include <cuda_fp16.h>
#include <math.h>
#include <stdint.h>

// Problem dims (fixed by the reference)
#define Bx   4
#define Tx   2048
#define Mx   2048
#define Dx   1024
#define Hx   16
#define DKx  64
#define DFFx 4096
#define NX   (Bx*Tx)   // 8192 rows of x
#define NM   (Bx*Mx)   // 8192 rows of mem

#define NEGINF (__int_as_float(0xff800000))

// ---------------------------------------------------------------------------
// Scratch (device globals; allocation-free per harness rules)
// ---------------------------------------------------------------------------
__device__ float  g_qkv[NX * 3 * Dx];     // self-attn qkv (fp32)
__device__ float  g_y  [NX * Dx];         // qc (fp32, GEMM out -> attn Q)
__device__ float  g_x  [NX * Dx];         // running residual (fp32)
__device__ float  g_kv [NM * 2 * Dx];     // cross kv (fp32)
__device__ __half g_hh [NX * Dx];         // LN outputs (f16, GEMM A)
__device__ __half g_yh [NX * Dx];         // self-attn out (f16, GEMM A)
__device__ __half g_ych[NX * Dx];         // cross-attn out (f16, GEMM A)
__device__ __half g_ffh[NX * DFFx];       // ffn hidden (f16, GEMM A)
__device__ __half g_wh [16 * 1024 * 1024];// f16 weights (concatenated)
__device__ __half g_memh[NM * Dx];        // f16 mem

// Offsets into g_wh (elements)
#define WOFF_QKV    0
#define WOFF_PROJ   (3*1024*1024)
#define WOFF_CAQ    (4*1024*1024)
#define WOFF_CAKV   (5*1024*1024)
#define WOFF_CAPROJ (7*1024*1024)
#define WOFF_FF1    (8*1024*1024)
#define WOFF_FF2    (12*1024*1024)

__device__ __forceinline__ uint32_t h2u(__half2 h) {
    return *reinterpret_cast<uint32_t*>(&h);
}

// ---------------------------------------------------------------------------
// Bulk fp32 -> fp16 conversion, 8 elems/thread, n % 2048 == 0
// ---------------------------------------------------------------------------
__global__ __launch_bounds__(256) void cvt_h_kernel(
    const float* __restrict__ src, __half* __restrict__ dst)
{
    long long i = ((long long)blockIdx.x * 256 + threadIdx.x) * 8;
    float4 a = *(const float4*)(src + i);
    float4 b = *(const float4*)(src + i + 4);
    uint4 u;
    u.x = h2u(__floats2half2_rn(a.x, a.y));
    u.y = h2u(__floats2half2_rn(a.z, a.w));
    u.z = h2u(__floats2half2_rn(b.x, b.y));
    u.w = h2u(__floats2half2_rn(b.z, b.w));
    *(uint4*)(dst + i) = u;
}

// ---------------------------------------------------------------------------
// LayerNorm: one block per row, D = 1024, 256 threads. f16 output (GEMM A).
// ---------------------------------------------------------------------------
__global__ __launch_bounds__(256) void ln_kernel(
    const float* __restrict__ X, const float* __restrict__ w,
    const float* __restrict__ b, __half* __restrict__ out)
{
    long long row = blockIdx.x;
    const float* xr = X + row * Dx;
    int t = threadIdx.x;
    float4 v = *(const float4*)(xr + t * 4);
    float s  = v.x + v.y + v.z + v.w;
    float ss = v.x*v.x + v.y*v.y + v.z*v.z + v.w*v.w;
    #pragma unroll
    for (int o = 16; o > 0; o >>= 1) {
        s  += __shfl_xor_sync(0xffffffffu, s, o);
        ss += __shfl_xor_sync(0xffffffffu, ss, o);
    }
    __shared__ float rs[8], rss[8];
    __shared__ float smu, srstd;
    if ((t & 31) == 0) { rs[t >> 5] = s; rss[t >> 5] = ss; }
    __syncthreads();
    if (t == 0) {
        float S = 0.f, SS = 0.f;
        #pragma unroll
        for (int i = 0; i < 8; i++) { S += rs[i]; SS += rss[i]; }
        float mu  = S * (1.0f / Dx);
        float var = SS * (1.0f / Dx) - mu * mu;
        smu = mu; srstd = rsqrtf(var + 1e-5f);
    }
    __syncthreads();
    float mu = smu, r = srstd;
    float4 wv = *(const float4*)(w + t * 4);
    float4 bv = *(const float4*)(b + t * 4);
    uint2 u;
    u.x = h2u(__floats2half2_rn((v.x - mu) * r * wv.x + bv.x,
                                (v.y - mu) * r * wv.y + bv.y));
    u.y = h2u(__floats2half2_rn((v.z - mu) * r * wv.z + bv.z,
                                (v.w - mu) * r * wv.w + bv.w));
    *(uint2*)(out + row * Dx + t * 4) = u;
}

// ---------------------------------------------------------------------------
// FP16 tensor-core GEMM: C[M,N] = A[M,K] @ W[K,N] + bias (+gelu) (+residual)
// A, W are __half. 128x128 tile, BK=32, 3-stage cp.async, 256 threads
// (2x4 warp grid, 64x32 warp tiles), ldmatrix + mma.m16n8k16.f16.f32.
// Static smem = exactly 48KB. XOR-swizzled smem, conflict-free.
// ---------------------------------------------------------------------------
__device__ __forceinline__ float gelu_exact(float v) {
    return 0.5f * v * (1.0f + erff(v * 0.7071067811865476f));
}
__device__ __forceinline__ void cp16(uint32_t dst, const void* src) {
    asm volatile("cp.async.cg.shared.global [%0], [%1], 16;\n" :: "r"(dst), "l"(src));
}
__device__ __forceinline__ void ldsm4(uint32_t* r, uint32_t addr) {
    asm volatile("ldmatrix.sync.aligned.m8n8.x4.shared.b16 {%0,%1,%2,%3}, [%4];"
        : "=r"(r[0]), "=r"(r[1]), "=r"(r[2]), "=r"(r[3]) : "r"(addr));
}
__device__ __forceinline__ void ldsm4t(uint32_t* r, uint32_t addr) {
    asm volatile("ldmatrix.sync.aligned.m8n8.x4.trans.shared.b16 {%0,%1,%2,%3}, [%4];"
        : "=r"(r[0]), "=r"(r[1]), "=r"(r[2]), "=r"(r[3]) : "r"(addr));
}
__device__ __forceinline__ void mma_f16(float* d, const uint32_t* a, const uint32_t* b) {
    asm volatile(
        "mma.sync.aligned.m16n8k16.row.col.f32.f16.f16.f32 "
        "{%0,%1,%2,%3}, {%4,%5,%6,%7}, {%8,%9}, {%0,%1,%2,%3};\n"
        : "+f"(d[0]), "+f"(d[1]), "+f"(d[2]), "+f"(d[3])
        : "r"(a[0]), "r"(a[1]), "r"(a[2]), "r"(a[3]),
          "r"(b[0]), "r"(b[1]));
}

// Smem layout (halves): A stages at [stage*4096], B stages at [12288 + stage*4096]
// A tile [128][32]: byte = m*64 + ((k>>3 ^ ((m>>1)&3))<<4) + (k&7)*2
// B tile [32][128]: byte = k*256 + (((n>>3) ^ (k&7))<<4) + (n&7)*2
__global__ __launch_bounds__(256) void gemm_f16(
    const __half* __restrict__ A, const __half* __restrict__ W,
    const float* __restrict__ bias, const float* __restrict__ resid,
    float* __restrict__ C, __half* __restrict__ Ch,
    int K, int N, int dogelu)
{
    __shared__ __half smem[3 * 4096 + 3 * 4096];

    const int tid  = threadIdx.x;
    const int lane = tid & 31;
    const int warp = tid >> 5;
    const int wm = (warp & 1) * 64;     // warp M offset within tile
    const int wn = (warp >> 1) * 32;    // warp N offset within tile
    const int gid = lane >> 2;
    const int tig = lane & 3;

    const int m0 = blockIdx.y * 128, n0 = blockIdx.x * 128;

    float acc[4][4][4];
    #pragma unroll
    for (int mt = 0; mt < 4; mt++)
        #pragma unroll
        for (int nt = 0; nt < 4; nt++)
            #pragma unroll
            for (int e = 0; e < 4; e++) acc[mt][nt][e] = 0.f;

    const uint32_t sbase = (uint32_t)__cvta_generic_to_shared(smem);

    // cp.async mappings (2 A chunks + 2 B chunks per thread per stage)
    #define PF(stg, kk0)                                                         \
    {                                                                            \
        _Pragma("unroll")                                                        \
        for (int half_ = 0; half_ < 2; half_++) {                                \
            int ch = tid + half_ * 256;                                          \
            int m = ch >> 2, c = ch & 3;                                         \
            cp16(sbase + (stg) * 8192 + m * 64 + ((c ^ ((m >> 1) & 3)) << 4),    \
                 A + (long long)(m0 + m) * K + (kk0) + c * 8);                   \
        }                                                                        \
        _Pragma("unroll")                                                        \
        for (int half_ = 0; half_ < 2; half_++) {                                \
            int ch = tid + half_ * 256;                                          \
            int k = ch >> 4, cn = ch & 15;                                       \
            cp16(sbase + 24576 + (stg) * 8192 + k * 256 + ((cn ^ (k & 7)) << 4), \
                 W + (long long)((kk0) + k) * N + n0 + cn * 8);                  \
        }                                                                        \
    }

    const int KT = K >> 5;
    PF(0, 0);
    asm volatile("cp.async.commit_group;\n");
    PF(1, 32);
    asm volatile("cp.async.commit_group;\n");

    // Per-thread ldmatrix address components (constant across iterations)
    const int lmat = lane >> 3, lrow = lane & 7;

    for (int kt = 0; kt < KT; kt++) {
        asm volatile("cp.async.wait_group 1;\n");
        __syncthreads();
        if (kt + 2 < KT) { PF((kt + 2) % 3, (kt + 2) * 32); }
        asm volatile("cp.async.commit_group;\n");

        const int stg = kt % 3;
        const uint32_t abase = sbase + stg * 8192;
        const uint32_t bbase = sbase + 24576 + stg * 8192;

        #pragma unroll
        for (int kk = 0; kk < 2; kk++) {
            // B fragments: 2 x ldmatrix.x4.trans -> 4 n-tiles x 2 regs
            uint32_t bf[4][2];
            #pragma unroll
            for (int p = 0; p < 2; p++) {
                int k = kk * 16 + (lmat & 1) * 8 + lrow;
                int cn = ((wn + p * 16) >> 3) + (lmat >> 1);
                uint32_t r[4];
                ldsm4t(r, bbase + k * 256 + ((cn ^ (k & 7)) << 4));
                bf[2 * p][0] = r[0]; bf[2 * p][1] = r[1];
                bf[2 * p + 1][0] = r[2]; bf[2 * p + 1][1] = r[3];
            }
            // A fragments: 4 x ldmatrix.x4
            uint32_t af[4][4];
            #pragma unroll
            for (int mt = 0; mt < 4; mt++) {
                int m = wm + mt * 16 + (lmat & 1) * 8 + lrow;
                int kc = kk * 2 + (lmat >> 1);
                ldsm4(af[mt], abase + m * 64 + ((kc ^ ((m >> 1) & 3)) << 4));
            }
            #pragma unroll
            for (int mt = 0; mt < 4; mt++)
                #pragma unroll
                for (int nt = 0; nt < 4; nt++)
                    mma_f16(acc[mt][nt], af[mt], bf[nt]);
        }
    }

    // Epilogue: bias (+gelu) (+residual); fp32 and/or f16 stores
    #pragma unroll
    for (int mt = 0; mt < 4; mt++) {
        #pragma unroll
        for (int nt = 0; nt < 4; nt++) {
            int c = n0 + wn + nt * 8 + 2 * tig;
            float2 bv = *(const float2*)(bias + c);
            #pragma unroll
            for (int hh = 0; hh < 2; hh++) {
                long long r = m0 + wm + mt * 16 + gid + hh * 8;
                float2 v;
                v.x = acc[mt][nt][2 * hh + 0] + bv.x;
                v.y = acc[mt][nt][2 * hh + 1] + bv.y;
                if (dogelu) { v.x = gelu_exact(v.x); v.y = gelu_exact(v.y); }
                if (resid) {
                    float2 rv = *(const float2*)(resid + r * N + c);
                    v.x += rv.x; v.y += rv.y;
                }
                if (C)  *(float2*)(C + r * N + c) = v;
                if (Ch) *(__half2*)(Ch + r * N + c) = __floats2half2_rn(v.x, v.y);
            }
        }
    }
}

// ---------------------------------------------------------------------------
// Flash attention (fp32 SIMT), f16 output (feeds GEMM A only).
// block = (b,h) x 64-query tile; BK = 64 keys. Static smem = 48KB.
// ---------------------------------------------------------------------------
__global__ __launch_bounds__(256) void attn_kernel(
    const float* __restrict__ Qp, int ldq, long long qbs,
    const float* __restrict__ Kp, int ldk, long long kbs,
    const float* __restrict__ Vp, int ldv, long long vbs,
    __half* __restrict__ Op, int ldo, long long obs,
    const int* __restrict__ maskp, int Mk, int causal)
{
    __shared__ float Qs [64 * 64];
    __shared__ float KsT[64 * 64];   // xor-swizzled K^T; reused as P
    __shared__ float Vs [64 * 64];

    int tid = threadIdx.x;
    int tx = tid & 15, ty = tid >> 4;
    int b = blockIdx.x >> 4, h = blockIdx.x & 15;
    int q0 = blockIdx.y * 64;

    const float* Q  = Qp + b * qbs + h * 64;
    const float* Kb = Kp + b * kbs + h * 64;
    const float* Vb = Vp + b * vbs + h * 64;
    const int*   mk = maskp ? (maskp + (long long)b * Mk) : (const int*)0;

    #pragma unroll
    for (int p = 0; p < 4; p++) {
        int idx = tid + 256 * p;
        int r = idx >> 4, c4 = (idx & 15) * 4;
        float4 qv = *(const float4*)(Q + (long long)(q0 + r) * ldq + c4);
        *(float4*)&Qs[r * 64 + c4] = qv;
    }

    float m_i[4], l_i[4], acc[4][4];
    #pragma unroll
    for (int i = 0; i < 4; i++) {
        m_i[i] = -1e30f; l_i[i] = 0.f;
        #pragma unroll
        for (int j = 0; j < 4; j++) acc[i][j] = 0.f;
    }

    int nkt = causal ? (blockIdx.y + 1) : (Mk / 64);
    for (int kt = 0; kt < nkt; kt++) {
        int k0 = kt * 64;
        __syncthreads();

        #pragma unroll
        for (int p = 0; p < 4; p++) {
            int idx = tid + 256 * p;
            int key = idx >> 4, c4 = (idx & 15) * 4;
            float4 kv = *(const float4*)(Kb + (long long)(k0 + key) * ldk + c4);
            float kvarr[4] = {kv.x, kv.y, kv.z, kv.w};
            #pragma unroll
            for (int e = 0; e < 4; e++) {
                int d = c4 + e;
                KsT[d * 64 + (((key >> 2) ^ (d & 15)) << 2) + (key & 3)] = kvarr[e];
            }
            float4 vv = *(const float4*)(Vb + (long long)(k0 + key) * ldv + c4);
            *(float4*)&Vs[key * 64 + c4] = vv;
        }
        __syncthreads();

        float s[4][4];
        #pragma unroll
        for (int i = 0; i < 4; i++)
            #pragma unroll
            for (int j = 0; j < 4; j++) s[i][j] = 0.f;
        #pragma unroll 16
        for (int d = 0; d < 64; d++) {
            float4 k4 = *(const float4*)&KsT[d * 64 + ((tx ^ (d & 15)) << 2)];
            float a0 = Qs[(4 * ty + 0) * 64 + d];
            float a1 = Qs[(4 * ty + 1) * 64 + d];
            float a2 = Qs[(4 * ty + 2) * 64 + d];
            float a3 = Qs[(4 * ty + 3) * 64 + d];
            s[0][0] += a0 * k4.x; s[0][1] += a0 * k4.y; s[0][2] += a0 * k4.z; s[0][3] += a0 * k4.w;
            s[1][0] += a1 * k4.x; s[1][1] += a1 * k4.y; s[1][2] += a1 * k4.z; s[1][3] += a1 * k4.w;
            s[2][0] += a2 * k4.x; s[2][1] += a2 * k4.y; s[2][2] += a2 * k4.z; s[2][3] += a2 * k4.w;
            s[3][0] += a3 * k4.x; s[3][1] += a3 * k4.y; s[3][2] += a3 * k4.z; s[3][3] += a3 * k4.w;
        }

        bool diag = (causal != 0) && (k0 == q0);
        int mval[4] = {1, 1, 1, 1};
        if (mk) {
            #pragma unroll
            for (int j = 0; j < 4; j++) mval[j] = mk[k0 + 4 * tx + j];
        }
        #pragma unroll
        for (int i = 0; i < 4; i++)
            #pragma unroll
            for (int j = 0; j < 4; j++) {
                float sv = s[i][j] * 0.125f;
                if (diag && (k0 + 4 * tx + j > q0 + 4 * ty + i)) sv = NEGINF;
                if (mk && mval[j] == 0) sv = NEGINF;
                s[i][j] = sv;
            }
        __syncthreads();

        #pragma unroll
        for (int i = 0; i < 4; i++) {
            float rmax = fmaxf(fmaxf(s[i][0], s[i][1]), fmaxf(s[i][2], s[i][3]));
            #pragma unroll
            for (int o = 1; o < 16; o <<= 1)
                rmax = fmaxf(rmax, __shfl_xor_sync(0xffffffffu, rmax, o));
            float mnew = fmaxf(m_i[i], rmax);
            float sc = __expf(m_i[i] - mnew);
            float p0 = __expf(s[i][0] - mnew);
            float p1 = __expf(s[i][1] - mnew);
            float p2 = __expf(s[i][2] - mnew);
            float p3 = __expf(s[i][3] - mnew);
            float rsum = p0 + p1 + p2 + p3;
            #pragma unroll
            for (int o = 1; o < 16; o <<= 1)
                rsum += __shfl_xor_sync(0xffffffffu, rsum, o);
            l_i[i] = l_i[i] * sc + rsum;
            m_i[i] = mnew;
            acc[i][0] *= sc; acc[i][1] *= sc; acc[i][2] *= sc; acc[i][3] *= sc;
            int r = 4 * ty + i;
            KsT[r * 64 + 4 * tx + 0] = p0;
            KsT[r * 64 + 4 * tx + 1] = p1;
            KsT[r * 64 + 4 * tx + 2] = p2;
            KsT[r * 64 + 4 * tx + 3] = p3;
        }
        __syncthreads();

        #pragma unroll 16
        for (int kk = 0; kk < 64; kk++) {
            float4 v4 = *(const float4*)&Vs[kk * 64 + 4 * tx];
            float p0 = KsT[(4 * ty + 0) * 64 + kk];
            float p1 = KsT[(4 * ty + 1) * 64 + kk];
            float p2 = KsT[(4 * ty + 2) * 64 + kk];
            float p3 = KsT[(4 * ty + 3) * 64 + kk];
            acc[0][0] += p0 * v4.x; acc[0][1] += p0 * v4.y; acc[0][2] += p0 * v4.z; acc[0][3] += p0 * v4.w;
            acc[1][0] += p1 * v4.x; acc[1][1] += p1 * v4.y; acc[1][2] += p1 * v4.z; acc[1][3] += p1 * v4.w;
            acc[2][0] += p2 * v4.x; acc[2][1] += p2 * v4.y; acc[2][2] += p2 * v4.z; acc[2][3] += p2 * v4.w;
            acc[3][0] += p3 * v4.x; acc[3][1] += p3 * v4.y; acc[3][2] += p3 * v4.z; acc[3][3] += p3 * v4.w;
        }
    }

    // Normalize and write f16 output
    #pragma unroll
    for (int i = 0; i < 4; i++) {
        float inv = 1.0f / l_i[i];
        uint2 u;
        u.x = h2u(__floats2half2_rn(acc[i][0] * inv, acc[i][1] * inv));
        u.y = h2u(__floats2half2_rn(acc[i][2] * inv, acc[i][3] * inv));
        *(uint2*)(Op + b * obs + (long long)(q0 + 4 * ty + i) * ldo + h * 64 + 4 * tx) = u;
    }
}

// ---------------------------------------------------------------------------
// Launch: graph-capturable kernel launches on the default stream
// ---------------------------------------------------------------------------
extern "C" void kernel_launch(void* const* d_in, const int* in_sizes, int n_in,
                              void* d_out, int out_size)
{
    const float* x         = (const float*)d_in[0];
    const float* mem       = (const float*)d_in[1];
    const int*   mem_mask  = (const int*)  d_in[2];
    const float* ln1_w     = (const float*)d_in[3];
    const float* ln1_b     = (const float*)d_in[4];
    const float* sa_qkv_w  = (const float*)d_in[5];
    const float* sa_qkv_b  = (const float*)d_in[6];
    const float* sa_proj_w = (const float*)d_in[7];
    const float* sa_proj_b = (const float*)d_in[8];
    const float* lnm_w     = (const float*)d_in[9];
    const float* lnm_b     = (const float*)d_in[10];
    const float* ca_q_w    = (const float*)d_in[11];
    const float* ca_q_b    = (const float*)d_in[12];
    const float* ca_kv_w   = (const float*)d_in[13];
    const float* ca_kv_b   = (const float*)d_in[14];
    const float* ca_proj_w = (const float*)d_in[15];
    const float* ca_proj_b = (const float*)d_in[16];
    const float* ln2_w     = (const float*)d_in[17];
    const float* ln2_b     = (const float*)d_in[18];
    const float* ff1_w     = (const float*)d_in[19];
    const float* ff1_b     = (const float*)d_in[20];
    const float* ff2_w     = (const float*)d_in[21];
    const float* ff2_b     = (const float*)d_in[22];
    float* out = (float*)d_out;

    float *qkv, *y, *xr, *kv;
    __half *hh, *yh, *ych, *ffh, *wh, *memh;
    cudaGetSymbolAddress((void**)&qkv,  g_qkv);
    cudaGetSymbolAddress((void**)&y,    g_y);
    cudaGetSymbolAddress((void**)&xr,   g_x);
    cudaGetSymbolAddress((void**)&kv,   g_kv);
    cudaGetSymbolAddress((void**)&hh,   g_hh);
    cudaGetSymbolAddress((void**)&yh,   g_yh);
    cudaGetSymbolAddress((void**)&ych,  g_ych);
    cudaGetSymbolAddress((void**)&ffh,  g_ffh);
    cudaGetSymbolAddress((void**)&wh,   g_wh);
    cudaGetSymbolAddress((void**)&memh, g_memh);

    // 0) One-pass f16 conversion of weights + mem
    cvt_h_kernel<<<3 * Dx * Dx / 2048, 256>>>(sa_qkv_w,  wh + WOFF_QKV);
    cvt_h_kernel<<<Dx * Dx / 2048,     256>>>(sa_proj_w, wh + WOFF_PROJ);
    cvt_h_kernel<<<Dx * Dx / 2048,     256>>>(ca_q_w,    wh + WOFF_CAQ);
    cvt_h_kernel<<<2 * Dx * Dx / 2048, 256>>>(ca_kv_w,   wh + WOFF_CAKV);
    cvt_h_kernel<<<Dx * Dx / 2048,     256>>>(ca_proj_w, wh + WOFF_CAPROJ);
    cvt_h_kernel<<<Dx * DFFx / 2048,   256>>>(ff1_w,     wh + WOFF_FF1);
    cvt_h_kernel<<<DFFx * Dx / 2048,   256>>>(ff2_w,     wh + WOFF_FF2);
    cvt_h_kernel<<<NM * Dx / 2048,     256>>>(mem,       memh);

    // 1) hh = LN(x)
    ln_kernel<<<NX, 256>>>(x, ln1_w, ln1_b, hh);
    // 2) qkv = hh @ Wqkv + b (fp32)
    gemm_f16<<<dim3(3 * Dx / 128, NX / 128), 256>>>(hh, wh + WOFF_QKV, sa_qkv_b, 0, qkv, 0, Dx, 3 * Dx, 0);
    // 3) yh = causal self-attention(qkv)  (f16 out)
    attn_kernel<<<dim3(Bx * Hx, Tx / 64), 256>>>(
        qkv,            3 * Dx, (long long)Tx * 3 * Dx,
        qkv + Dx,       3 * Dx, (long long)Tx * 3 * Dx,
        qkv + 2 * Dx,   3 * Dx, (long long)Tx * 3 * Dx,
        yh,             Dx,     (long long)Tx * Dx,
        (const int*)0, Tx, 1);
    // 4) x1 = x + yh @ Wproj + b
    gemm_f16<<<dim3(Dx / 128, NX / 128), 256>>>(yh, wh + WOFF_PROJ, sa_proj_b, x, xr, 0, Dx, Dx, 0);
    // 5) hh = LN(x1)
    ln_kernel<<<NX, 256>>>(xr, lnm_w, lnm_b, hh);
    // 6) qc = hh @ Wq + b (fp32, into g_y)
    gemm_f16<<<dim3(Dx / 128, NX / 128), 256>>>(hh, wh + WOFF_CAQ, ca_q_b, 0, y, 0, Dx, Dx, 0);
    // 7) kv = mem @ Wkv + b (fp32)
    gemm_f16<<<dim3(2 * Dx / 128, NM / 128), 256>>>(memh, wh + WOFF_CAKV, ca_kv_b, 0, kv, 0, Dx, 2 * Dx, 0);
    // 8) ych = cross-attention(qc, kv, mem_mask)  (f16 out)
    attn_kernel<<<dim3(Bx * Hx, Tx / 64), 256>>>(
        y,         Dx,     (long long)Tx * Dx,
        kv,        2 * Dx, (long long)Mx * 2 * Dx,
        kv + Dx,   2 * Dx, (long long)Mx * 2 * Dx,
        ych,       Dx,     (long long)Tx * Dx,
        mem_mask, Mx, 0);
    // 9) x2 = x1 + ych @ Wcp + b (in-place residual)
    gemm_f16<<<dim3(Dx / 128, NX / 128), 256>>>(ych, wh + WOFF_CAPROJ, ca_proj_b, xr, xr, 0, Dx, Dx, 0);
    // 10) hh = LN(x2)
    ln_kernel<<<NX, 256>>>(xr, ln2_w, ln2_b, hh);
    // 11) ffh = gelu(hh @ W1 + b)  (f16 out only)
    gemm_f16<<<dim3(DFFx / 128, NX / 128), 256>>>(hh, wh + WOFF_FF1, ff1_b, 0, 0, ffh, Dx, DFFx, 1);
    // 12) out = x2 + ffh @ W2 + b  (fp32 final)
    gemm_f16<<<dim3(Dx / 128, NX / 128), 256>>>(ffh, wh + WOFF_FF2, ff2_b, xr, out, 0, DFFx, Dx, 0);
}

// round 6
// speedup vs baseline: 7.7289x; 2.8861x over previous
#include <cuda_runtime.h>
#include <cuda_fp16.h>
#include <math.h>
#include <stdint.h>

// Problem dims (fixed by the reference)
#define Bx   4
#define Tx   2048
#define Mx   2048
#define Dx   1024
#define Hx   16
#define DKx  64
#define DFFx 4096
#define NX   (Bx*Tx)   // 8192 rows of x
#define NM   (Bx*Mx)   // 8192 rows of mem

#define NEGINF (__int_as_float(0xff800000))

// ---------------------------------------------------------------------------
// Scratch (device globals; allocation-free per harness rules)
// ---------------------------------------------------------------------------
__device__ float  g_x  [NX * Dx];          // running residual (fp32)
__device__ __half g_qkvh[NX * 3 * Dx];     // self-attn qkv (f16)
__device__ __half g_qch [NX * Dx];         // cross-attn q (f16)
__device__ __half g_kvh [NM * 2 * Dx];     // cross kv (f16)
__device__ __half g_hh [NX * Dx];          // LN outputs (f16, GEMM A)
__device__ __half g_yh [NX * Dx];          // self-attn out (f16, GEMM A)
__device__ __half g_ych[NX * Dx];          // cross-attn out (f16, GEMM A)
__device__ __half g_ffh[NX * DFFx];        // ffn hidden (f16, GEMM A)
__device__ __half g_wh [16 * 1024 * 1024]; // f16 weights (concatenated)
__device__ __half g_memh[NM * Dx];         // f16 mem

// Offsets into g_wh (elements)
#define WOFF_QKV    0
#define WOFF_PROJ   (3*1024*1024)
#define WOFF_CAQ    (4*1024*1024)
#define WOFF_CAKV   (5*1024*1024)
#define WOFF_CAPROJ (7*1024*1024)
#define WOFF_FF1    (8*1024*1024)
#define WOFF_FF2    (12*1024*1024)

__device__ __forceinline__ uint32_t h2u(__half2 h) {
    return *reinterpret_cast<uint32_t*>(&h);
}

// ---------------------------------------------------------------------------
// Bulk fp32 -> fp16 conversion, 8 elems/thread, n % 2048 == 0
// ---------------------------------------------------------------------------
__global__ __launch_bounds__(256) void cvt_h_kernel(
    const float* __restrict__ src, __half* __restrict__ dst)
{
    long long i = ((long long)blockIdx.x * 256 + threadIdx.x) * 8;
    float4 a = *(const float4*)(src + i);
    float4 b = *(const float4*)(src + i + 4);
    uint4 u;
    u.x = h2u(__floats2half2_rn(a.x, a.y));
    u.y = h2u(__floats2half2_rn(a.z, a.w));
    u.z = h2u(__floats2half2_rn(b.x, b.y));
    u.w = h2u(__floats2half2_rn(b.z, b.w));
    *(uint4*)(dst + i) = u;
}

// ---------------------------------------------------------------------------
// LayerNorm: one block per row, D = 1024, 256 threads. f16 output (GEMM A).
// ---------------------------------------------------------------------------
__global__ __launch_bounds__(256) void ln_kernel(
    const float* __restrict__ X, const float* __restrict__ w,
    const float* __restrict__ b, __half* __restrict__ out)
{
    long long row = blockIdx.x;
    const float* xr = X + row * Dx;
    int t = threadIdx.x;
    float4 v = *(const float4*)(xr + t * 4);
    float s  = v.x + v.y + v.z + v.w;
    float ss = v.x*v.x + v.y*v.y + v.z*v.z + v.w*v.w;
    #pragma unroll
    for (int o = 16; o > 0; o >>= 1) {
        s  += __shfl_xor_sync(0xffffffffu, s, o);
        ss += __shfl_xor_sync(0xffffffffu, ss, o);
    }
    __shared__ float rs[8], rss[8];
    __shared__ float smu, srstd;
    if ((t & 31) == 0) { rs[t >> 5] = s; rss[t >> 5] = ss; }
    __syncthreads();
    if (t == 0) {
        float S = 0.f, SS = 0.f;
        #pragma unroll
        for (int i = 0; i < 8; i++) { S += rs[i]; SS += rss[i]; }
        float mu  = S * (1.0f / Dx);
        float var = SS * (1.0f / Dx) - mu * mu;
        smu = mu; srstd = rsqrtf(var + 1e-5f);
    }
    __syncthreads();
    float mu = smu, r = srstd;
    float4 wv = *(const float4*)(w + t * 4);
    float4 bv = *(const float4*)(b + t * 4);
    uint2 u;
    u.x = h2u(__floats2half2_rn((v.x - mu) * r * wv.x + bv.x,
                                (v.y - mu) * r * wv.y + bv.y));
    u.y = h2u(__floats2half2_rn((v.z - mu) * r * wv.z + bv.z,
                                (v.w - mu) * r * wv.w + bv.w));
    *(uint2*)(out + row * Dx + t * 4) = u;
}

// ---------------------------------------------------------------------------
// Common PTX helpers
// ---------------------------------------------------------------------------
__device__ __forceinline__ float gelu_exact(float v) {
    return 0.5f * v * (1.0f + erff(v * 0.7071067811865476f));
}
__device__ __forceinline__ void cp16(uint32_t dst, const void* src) {
    asm volatile("cp.async.cg.shared.global [%0], [%1], 16;\n" :: "r"(dst), "l"(src));
}
__device__ __forceinline__ void ldsm4(uint32_t* r, uint32_t addr) {
    asm volatile("ldmatrix.sync.aligned.m8n8.x4.shared.b16 {%0,%1,%2,%3}, [%4];"
        : "=r"(r[0]), "=r"(r[1]), "=r"(r[2]), "=r"(r[3]) : "r"(addr));
}
__device__ __forceinline__ void ldsm4t(uint32_t* r, uint32_t addr) {
    asm volatile("ldmatrix.sync.aligned.m8n8.x4.trans.shared.b16 {%0,%1,%2,%3}, [%4];"
        : "=r"(r[0]), "=r"(r[1]), "=r"(r[2]), "=r"(r[3]) : "r"(addr));
}
__device__ __forceinline__ void mma_f16(float* d, const uint32_t* a, uint32_t b0, uint32_t b1) {
    asm volatile(
        "mma.sync.aligned.m16n8k16.row.col.f32.f16.f16.f32 "
        "{%0,%1,%2,%3}, {%4,%5,%6,%7}, {%8,%9}, {%0,%1,%2,%3};\n"
        : "+f"(d[0]), "+f"(d[1]), "+f"(d[2]), "+f"(d[3])
        : "r"(a[0]), "r"(a[1]), "r"(a[2]), "r"(a[3]),
          "r"(b0), "r"(b1));
}

// ---------------------------------------------------------------------------
// FP16 tensor-core GEMM: C[M,N] = A[M,K] @ W[K,N] + bias (+gelu) (+residual)
// 128x128 tile, BK=32, 3-stage cp.async, 256 threads, ldmatrix + m16n8k16.
// ---------------------------------------------------------------------------
__global__ __launch_bounds__(256) void gemm_f16(
    const __half* __restrict__ A, const __half* __restrict__ W,
    const float* __restrict__ bias, const float* __restrict__ resid,
    float* __restrict__ C, __half* __restrict__ Ch,
    int K, int N, int dogelu)
{
    __shared__ __half smem[3 * 4096 + 3 * 4096];

    const int tid  = threadIdx.x;
    const int lane = tid & 31;
    const int warp = tid >> 5;
    const int wm = (warp & 1) * 64;
    const int wn = (warp >> 1) * 32;
    const int gid = lane >> 2;
    const int tig = lane & 3;

    const int m0 = blockIdx.y * 128, n0 = blockIdx.x * 128;

    float acc[4][4][4];
    #pragma unroll
    for (int mt = 0; mt < 4; mt++)
        #pragma unroll
        for (int nt = 0; nt < 4; nt++)
            #pragma unroll
            for (int e = 0; e < 4; e++) acc[mt][nt][e] = 0.f;

    const uint32_t sbase = (uint32_t)__cvta_generic_to_shared(smem);

    #define PF(stg, kk0)                                                         \
    {                                                                            \
        _Pragma("unroll")                                                        \
        for (int half_ = 0; half_ < 2; half_++) {                                \
            int ch = tid + half_ * 256;                                          \
            int m = ch >> 2, c = ch & 3;                                         \
            cp16(sbase + (stg) * 8192 + m * 64 + ((c ^ ((m >> 1) & 3)) << 4),    \
                 A + (long long)(m0 + m) * K + (kk0) + c * 8);                   \
        }                                                                        \
        _Pragma("unroll")                                                        \
        for (int half_ = 0; half_ < 2; half_++) {                                \
            int ch = tid + half_ * 256;                                          \
            int k = ch >> 4, cn = ch & 15;                                       \
            cp16(sbase + 24576 + (stg) * 8192 + k * 256 + ((cn ^ (k & 7)) << 4), \
                 W + (long long)((kk0) + k) * N + n0 + cn * 8);                  \
        }                                                                        \
    }

    const int KT = K >> 5;
    PF(0, 0);
    asm volatile("cp.async.commit_group;\n");
    PF(1, 32);
    asm volatile("cp.async.commit_group;\n");

    const int lmat = lane >> 3, lrow = lane & 7;

    for (int kt = 0; kt < KT; kt++) {
        asm volatile("cp.async.wait_group 1;\n");
        __syncthreads();
        if (kt + 2 < KT) { PF((kt + 2) % 3, (kt + 2) * 32); }
        asm volatile("cp.async.commit_group;\n");

        const int stg = kt % 3;
        const uint32_t abase = sbase + stg * 8192;
        const uint32_t bbase = sbase + 24576 + stg * 8192;

        #pragma unroll
        for (int kk = 0; kk < 2; kk++) {
            uint32_t bf[4][2];
            #pragma unroll
            for (int p = 0; p < 2; p++) {
                int k = kk * 16 + (lmat & 1) * 8 + lrow;
                int cn = ((wn + p * 16) >> 3) + (lmat >> 1);
                uint32_t r[4];
                ldsm4t(r, bbase + k * 256 + ((cn ^ (k & 7)) << 4));
                bf[2 * p][0] = r[0]; bf[2 * p][1] = r[1];
                bf[2 * p + 1][0] = r[2]; bf[2 * p + 1][1] = r[3];
            }
            uint32_t af[4][4];
            #pragma unroll
            for (int mt = 0; mt < 4; mt++) {
                int m = wm + mt * 16 + (lmat & 1) * 8 + lrow;
                int kc = kk * 2 + (lmat >> 1);
                ldsm4(af[mt], abase + m * 64 + ((kc ^ ((m >> 1) & 3)) << 4));
            }
            #pragma unroll
            for (int mt = 0; mt < 4; mt++)
                #pragma unroll
                for (int nt = 0; nt < 4; nt++)
                    mma_f16(acc[mt][nt], af[mt], bf[nt][0], bf[nt][1]);
        }
    }

    #pragma unroll
    for (int mt = 0; mt < 4; mt++) {
        #pragma unroll
        for (int nt = 0; nt < 4; nt++) {
            int c = n0 + wn + nt * 8 + 2 * tig;
            float2 bv = *(const float2*)(bias + c);
            #pragma unroll
            for (int hh = 0; hh < 2; hh++) {
                long long r = m0 + wm + mt * 16 + gid + hh * 8;
                float2 v;
                v.x = acc[mt][nt][2 * hh + 0] + bv.x;
                v.y = acc[mt][nt][2 * hh + 1] + bv.y;
                if (dogelu) { v.x = gelu_exact(v.x); v.y = gelu_exact(v.y); }
                if (resid) {
                    float2 rv = *(const float2*)(resid + r * N + c);
                    v.x += rv.x; v.y += rv.y;
                }
                if (C)  *(float2*)(C + r * N + c) = v;
                if (Ch) *(__half2*)(Ch + r * N + c) = __floats2half2_rn(v.x, v.y);
            }
        }
    }
}

// ---------------------------------------------------------------------------
// Tensor-core fp16 flash attention.
// Block = (b,h) x 64-query tile; 128 threads (4 warps x 16 rows).
// 64-key steps; K/V (+mask) double-buffered via cp.async; Q loaded once.
// S and O via mma.m16n8k16; P stays in registers (C-frag == next A-frag).
// Smem: Q 8KB + K 2x8KB + V 2x8KB + mask 512B = 41KB static.
// ---------------------------------------------------------------------------
__global__ __launch_bounds__(128) void attn_f16(
    const __half* __restrict__ Qp, int ldq, long long qbs,
    const __half* __restrict__ Kp, int ldk, long long kbs,
    const __half* __restrict__ Vp, int ldv, long long vbs,
    __half* __restrict__ Op, int ldo, long long obs,
    const int* __restrict__ maskp, int Mk, int causal)
{
    __shared__ __half Qs[64 * 64];
    __shared__ __half Ks[2][64 * 64];
    __shared__ __half Vs[2][64 * 64];
    __shared__ int    msks[2][64];

    const int tid  = threadIdx.x;
    const int lane = tid & 31;
    const int warp = tid >> 5;
    const int l15 = lane & 15, l16 = lane >> 4, l7 = lane & 7;
    const int gid = lane >> 2, tig = lane & 3;

    const int b = blockIdx.x >> 4, h = blockIdx.x & 15;
    const int q0 = blockIdx.y * 64;

    const __half* Q  = Qp + b * qbs + h * 64;
    const __half* Kb = Kp + b * kbs + h * 64;
    const __half* Vb = Vp + b * vbs + h * 64;
    const int*    mk = maskp ? (maskp + (long long)b * Mk) : (const int*)0;

    const uint32_t qbase = (uint32_t)__cvta_generic_to_shared(Qs);
    const uint32_t kbase = (uint32_t)__cvta_generic_to_shared(&Ks[0][0]);
    const uint32_t vbase = (uint32_t)__cvta_generic_to_shared(&Vs[0][0]);
    const uint32_t mbase = (uint32_t)__cvta_generic_to_shared(&msks[0][0]);

    // KV(+mask) prefetch into stage stg for key tile starting at key0
    #define PFKV(stg, key0)                                                        \
    {                                                                              \
        _Pragma("unroll")                                                          \
        for (int p = 0; p < 4; p++) {                                              \
            int ch = tid + p * 128;                                                \
            int r = ch >> 3, c = ch & 7;                                           \
            uint32_t so = r * 128 + ((c ^ (r & 7)) << 4);                          \
            cp16(kbase + (stg) * 8192 + so, Kb + (long long)((key0) + r) * ldk + c * 8); \
            cp16(vbase + (stg) * 8192 + so, Vb + (long long)((key0) + r) * ldv + c * 8); \
        }                                                                          \
        if (mk && tid < 16)                                                        \
            cp16(mbase + (stg) * 256 + tid * 16, mk + (key0) + tid * 4);           \
    }

    // Q tile: 512 chunks of 16B, 4 per thread
    #pragma unroll
    for (int p = 0; p < 4; p++) {
        int ch = tid + p * 128;
        int r = ch >> 3, c = ch & 7;
        cp16(qbase + r * 128 + ((c ^ (r & 7)) << 4),
             Q + (long long)(q0 + r) * ldq + c * 8);
    }
    PFKV(0, 0);
    asm volatile("cp.async.commit_group;\n");

    float m_i[2] = {-1e30f, -1e30f}, l_i[2] = {0.f, 0.f};
    float oacc[8][4];
    #pragma unroll
    for (int dt = 0; dt < 8; dt++)
        #pragma unroll
        for (int e = 0; e < 4; e++) oacc[dt][e] = 0.f;

    const int nkt = causal ? (blockIdx.y + 1) : (Mk >> 6);
    const int row0 = q0 + 16 * warp + gid;

    for (int kt = 0; kt < nkt; kt++) {
        if (kt + 1 < nkt) {
            PFKV((kt + 1) & 1, (kt + 1) * 64);
            asm volatile("cp.async.commit_group;\n");
            asm volatile("cp.async.wait_group 1;\n");
        } else {
            asm volatile("cp.async.wait_group 0;\n");
        }
        __syncthreads();

        const int stg = kt & 1;
        const uint32_t kb = kbase + stg * 8192;
        const uint32_t vb = vbase + stg * 8192;
        const int k0 = kt * 64;

        // ---- S = Q @ K^T (fp32 accum), 8 n-tiles ----
        float sc[8][4];
        #pragma unroll
        for (int nt = 0; nt < 8; nt++)
            #pragma unroll
            for (int e = 0; e < 4; e++) sc[nt][e] = 0.f;

        #pragma unroll
        for (int kk = 0; kk < 4; kk++) {
            uint32_t af[4];
            ldsm4(af, qbase + (16 * warp + l15) * 128 + (((2 * kk + l16) ^ l7) << 4));
            #pragma unroll
            for (int ng = 0; ng < 4; ng++) {
                uint32_t bf[4];
                ldsm4(bf, kb + (16 * ng + l15) * 128 + (((2 * kk + l16) ^ l7) << 4));
                mma_f16(sc[2 * ng],     af, bf[0], bf[2]);
                mma_f16(sc[2 * ng + 1], af, bf[1], bf[3]);
            }
        }

        // ---- scale + masks ----
        const bool diag = (causal != 0) && (kt == blockIdx.y);
        #pragma unroll
        for (int nt = 0; nt < 8; nt++) {
            #pragma unroll
            for (int e = 0; e < 4; e++) sc[nt][e] *= 0.125f;
            int key0 = nt * 8 + 2 * tig;
            if (mk) {
                if (!msks[stg][key0])     { sc[nt][0] = NEGINF; sc[nt][2] = NEGINF; }
                if (!msks[stg][key0 + 1]) { sc[nt][1] = NEGINF; sc[nt][3] = NEGINF; }
            }
            if (diag) {
                int gk0 = k0 + key0, gk1 = gk0 + 1;
                if (gk0 > row0)     sc[nt][0] = NEGINF;
                if (gk1 > row0)     sc[nt][1] = NEGINF;
                if (gk0 > row0 + 8) sc[nt][2] = NEGINF;
                if (gk1 > row0 + 8) sc[nt][3] = NEGINF;
            }
        }

        // ---- online softmax (fp32); pack P to f16 A-fragments ----
        float rmax0 = -1e30f, rmax1 = -1e30f;
        #pragma unroll
        for (int nt = 0; nt < 8; nt++) {
            rmax0 = fmaxf(rmax0, fmaxf(sc[nt][0], sc[nt][1]));
            rmax1 = fmaxf(rmax1, fmaxf(sc[nt][2], sc[nt][3]));
        }
        rmax0 = fmaxf(rmax0, __shfl_xor_sync(0xffffffffu, rmax0, 1));
        rmax0 = fmaxf(rmax0, __shfl_xor_sync(0xffffffffu, rmax0, 2));
        rmax1 = fmaxf(rmax1, __shfl_xor_sync(0xffffffffu, rmax1, 1));
        rmax1 = fmaxf(rmax1, __shfl_xor_sync(0xffffffffu, rmax1, 2));

        float mn0 = fmaxf(m_i[0], rmax0), mn1 = fmaxf(m_i[1], rmax1);
        float sc0 = __expf(m_i[0] - mn0), sc1 = __expf(m_i[1] - mn1);
        float rs0 = 0.f, rs1 = 0.f;
        uint32_t p01[8], p23[8];
        #pragma unroll
        for (int nt = 0; nt < 8; nt++) {
            float e0 = __expf(sc[nt][0] - mn0);
            float e1 = __expf(sc[nt][1] - mn0);
            float e2 = __expf(sc[nt][2] - mn1);
            float e3 = __expf(sc[nt][3] - mn1);
            rs0 += e0 + e1; rs1 += e2 + e3;
            p01[nt] = h2u(__floats2half2_rn(e0, e1));
            p23[nt] = h2u(__floats2half2_rn(e2, e3));
        }
        rs0 += __shfl_xor_sync(0xffffffffu, rs0, 1);
        rs0 += __shfl_xor_sync(0xffffffffu, rs0, 2);
        rs1 += __shfl_xor_sync(0xffffffffu, rs1, 1);
        rs1 += __shfl_xor_sync(0xffffffffu, rs1, 2);

        l_i[0] = l_i[0] * sc0 + rs0;
        l_i[1] = l_i[1] * sc1 + rs1;
        m_i[0] = mn0; m_i[1] = mn1;
        #pragma unroll
        for (int dt = 0; dt < 8; dt++) {
            oacc[dt][0] *= sc0; oacc[dt][1] *= sc0;
            oacc[dt][2] *= sc1; oacc[dt][3] *= sc1;
        }

        // ---- O += P @ V ----
        #pragma unroll
        for (int j = 0; j < 4; j++) {
            uint32_t a[4] = { p01[2 * j], p23[2 * j], p01[2 * j + 1], p23[2 * j + 1] };
            #pragma unroll
            for (int g = 0; g < 4; g++) {
                uint32_t bf[4];
                ldsm4t(bf, vb + (16 * j + l15) * 128 + (((2 * g + l16) ^ l7) << 4));
                mma_f16(oacc[2 * g],     a, bf[0], bf[1]);
                mma_f16(oacc[2 * g + 1], a, bf[2], bf[3]);
            }
        }
        __syncthreads();
    }

    // ---- normalize + write f16 ----
    float inv0 = 1.0f / l_i[0], inv1 = 1.0f / l_i[1];
    #pragma unroll
    for (int dt = 0; dt < 8; dt++) {
        int col = h * 64 + dt * 8 + 2 * tig;
        *(__half2*)(Op + b * obs + (long long)row0 * ldo + col) =
            __floats2half2_rn(oacc[dt][0] * inv0, oacc[dt][1] * inv0);
        *(__half2*)(Op + b * obs + (long long)(row0 + 8) * ldo + col) =
            __floats2half2_rn(oacc[dt][2] * inv1, oacc[dt][3] * inv1);
    }
}

// ---------------------------------------------------------------------------
// Launch: graph-capturable kernel launches on the default stream
// ---------------------------------------------------------------------------
extern "C" void kernel_launch(void* const* d_in, const int* in_sizes, int n_in,
                              void* d_out, int out_size)
{
    const float* x         = (const float*)d_in[0];
    const float* mem       = (const float*)d_in[1];
    const int*   mem_mask  = (const int*)  d_in[2];
    const float* ln1_w     = (const float*)d_in[3];
    const float* ln1_b     = (const float*)d_in[4];
    const float* sa_qkv_w  = (const float*)d_in[5];
    const float* sa_qkv_b  = (const float*)d_in[6];
    const float* sa_proj_w = (const float*)d_in[7];
    const float* sa_proj_b = (const float*)d_in[8];
    const float* lnm_w     = (const float*)d_in[9];
    const float* lnm_b     = (const float*)d_in[10];
    const float* ca_q_w    = (const float*)d_in[11];
    const float* ca_q_b    = (const float*)d_in[12];
    const float* ca_kv_w   = (const float*)d_in[13];
    const float* ca_kv_b   = (const float*)d_in[14];
    const float* ca_proj_w = (const float*)d_in[15];
    const float* ca_proj_b = (const float*)d_in[16];
    const float* ln2_w     = (const float*)d_in[17];
    const float* ln2_b     = (const float*)d_in[18];
    const float* ff1_w     = (const float*)d_in[19];
    const float* ff1_b     = (const float*)d_in[20];
    const float* ff2_w     = (const float*)d_in[21];
    const float* ff2_b     = (const float*)d_in[22];
    float* out = (float*)d_out;

    float *xr;
    __half *qkvh, *qch, *kvh, *hh, *yh, *ych, *ffh, *wh, *memh;
    cudaGetSymbolAddress((void**)&xr,   g_x);
    cudaGetSymbolAddress((void**)&qkvh, g_qkvh);
    cudaGetSymbolAddress((void**)&qch,  g_qch);
    cudaGetSymbolAddress((void**)&kvh,  g_kvh);
    cudaGetSymbolAddress((void**)&hh,   g_hh);
    cudaGetSymbolAddress((void**)&yh,   g_yh);
    cudaGetSymbolAddress((void**)&ych,  g_ych);
    cudaGetSymbolAddress((void**)&ffh,  g_ffh);
    cudaGetSymbolAddress((void**)&wh,   g_wh);
    cudaGetSymbolAddress((void**)&memh, g_memh);

    // 0) One-pass f16 conversion of weights + mem
    cvt_h_kernel<<<3 * Dx * Dx / 2048, 256>>>(sa_qkv_w,  wh + WOFF_QKV);
    cvt_h_kernel<<<Dx * Dx / 2048,     256>>>(sa_proj_w, wh + WOFF_PROJ);
    cvt_h_kernel<<<Dx * Dx / 2048,     256>>>(ca_q_w,    wh + WOFF_CAQ);
    cvt_h_kernel<<<2 * Dx * Dx / 2048, 256>>>(ca_kv_w,   wh + WOFF_CAKV);
    cvt_h_kernel<<<Dx * Dx / 2048,     256>>>(ca_proj_w, wh + WOFF_CAPROJ);
    cvt_h_kernel<<<Dx * DFFx / 2048,   256>>>(ff1_w,     wh + WOFF_FF1);
    cvt_h_kernel<<<DFFx * Dx / 2048,   256>>>(ff2_w,     wh + WOFF_FF2);
    cvt_h_kernel<<<NM * Dx / 2048,     256>>>(mem,       memh);

    // 1) hh = LN(x)
    ln_kernel<<<NX, 256>>>(x, ln1_w, ln1_b, hh);
    // 2) qkvh = hh @ Wqkv + b (f16)
    gemm_f16<<<dim3(3 * Dx / 128, NX / 128), 256>>>(hh, wh + WOFF_QKV, sa_qkv_b, 0, 0, qkvh, Dx, 3 * Dx, 0);
    // 3) yh = causal self-attention(qkvh)
    attn_f16<<<dim3(Bx * Hx, Tx / 64), 128>>>(
        qkvh,          3 * Dx, (long long)Tx * 3 * Dx,
        qkvh + Dx,     3 * Dx, (long long)Tx * 3 * Dx,
        qkvh + 2 * Dx, 3 * Dx, (long long)Tx * 3 * Dx,
        yh,            Dx,     (long long)Tx * Dx,
        (const int*)0, Tx, 1);
    // 4) x1 = x + yh @ Wproj + b
    gemm_f16<<<dim3(Dx / 128, NX / 128), 256>>>(yh, wh + WOFF_PROJ, sa_proj_b, x, xr, 0, Dx, Dx, 0);
    // 5) hh = LN(x1)
    ln_kernel<<<NX, 256>>>(xr, lnm_w, lnm_b, hh);
    // 6) qch = hh @ Wq + b (f16)
    gemm_f16<<<dim3(Dx / 128, NX / 128), 256>>>(hh, wh + WOFF_CAQ, ca_q_b, 0, 0, qch, Dx, Dx, 0);
    // 7) kvh = mem @ Wkv + b (f16)
    gemm_f16<<<dim3(2 * Dx / 128, NM / 128), 256>>>(memh, wh + WOFF_CAKV, ca_kv_b, 0, 0, kvh, Dx, 2 * Dx, 0);
    // 8) ych = cross-attention(qch, kvh, mem_mask)
    attn_f16<<<dim3(Bx * Hx, Tx / 64), 128>>>(
        qch,       Dx,     (long long)Tx * Dx,
        kvh,       2 * Dx, (long long)Mx * 2 * Dx,
        kvh + Dx,  2 * Dx, (long long)Mx * 2 * Dx,
        ych,       Dx,     (long long)Tx * Dx,
        mem_mask, Mx, 0);
    // 9) x2 = x1 + ych @ Wcp + b (in-place residual)
    gemm_f16<<<dim3(Dx / 128, NX / 128), 256>>>(ych, wh + WOFF_CAPROJ, ca_proj_b, xr, xr, 0, Dx, Dx, 0);
    // 10) hh = LN(x2)
    ln_kernel<<<NX, 256>>>(xr, ln2_w, ln2_b, hh);
    // 11) ffh = gelu(hh @ W1 + b)
    gemm_f16<<<dim3(DFFx / 128, NX / 128), 256>>>(hh, wh + WOFF_FF1, ff1_b, 0, 0, ffh, Dx, DFFx, 1);
    // 12) out = x2 + ffh @ W2 + b (fp32 final)
    gemm_f16<<<dim3(Dx / 128, NX / 128), 256>>>(ffh, wh + WOFF_FF2, ff2_b, xr, out, 0, DFFx, Dx, 0);
}

// round 7
// speedup vs baseline: 8.1711x; 1.0572x over previous
#include <cuda_runtime.h>
#include <cuda_fp16.h>
#include <math.h>
#include <stdint.h>

// Problem dims (fixed by the reference)
#define Bx   4
#define Tx   2048
#define Mx   2048
#define Dx   1024
#define Hx   16
#define DKx  64
#define DFFx 4096
#define NX   (Bx*Tx)   // 8192 rows of x
#define NM   (Bx*Mx)   // 8192 rows of mem

#define NEGINF (__int_as_float(0xff800000))

// ---------------------------------------------------------------------------
// Scratch (device globals; allocation-free per harness rules)
// ---------------------------------------------------------------------------
__device__ float  g_x  [NX * Dx];          // running residual (fp32)
__device__ __half g_qkvh[NX * 3 * Dx];     // self-attn qkv (f16)
__device__ __half g_qch [NX * Dx];         // cross-attn q (f16)
__device__ __half g_kvh [NM * 2 * Dx];     // cross kv (f16)
__device__ __half g_hh [NX * Dx];          // LN outputs (f16, GEMM A)
__device__ __half g_yh [NX * Dx];          // self-attn out (f16, GEMM A)
__device__ __half g_ych[NX * Dx];          // cross-attn out (f16, GEMM A)
__device__ __half g_ffh[NX * DFFx];        // ffn hidden (f16, GEMM A)
__device__ __half g_wh [16 * 1024 * 1024]; // f16 weights (concatenated)
__device__ __half g_memh[NM * Dx];         // f16 mem

// Offsets into g_wh (elements)
#define WOFF_QKV    0
#define WOFF_PROJ   (3*1024*1024)
#define WOFF_CAQ    (4*1024*1024)
#define WOFF_CAKV   (5*1024*1024)
#define WOFF_CAPROJ (7*1024*1024)
#define WOFF_FF1    (8*1024*1024)
#define WOFF_FF2    (12*1024*1024)

#define GEMM_DSMEM 98304   // 3 stages x (16KB A + 16KB B)

__device__ __forceinline__ uint32_t h2u(__half2 h) {
    return *reinterpret_cast<uint32_t*>(&h);
}

// ---------------------------------------------------------------------------
// Bulk fp32 -> fp16 conversion, 8 elems/thread, n % 2048 == 0
// ---------------------------------------------------------------------------
__global__ __launch_bounds__(256) void cvt_h_kernel(
    const float* __restrict__ src, __half* __restrict__ dst)
{
    long long i = ((long long)blockIdx.x * 256 + threadIdx.x) * 8;
    float4 a = *(const float4*)(src + i);
    float4 b = *(const float4*)(src + i + 4);
    uint4 u;
    u.x = h2u(__floats2half2_rn(a.x, a.y));
    u.y = h2u(__floats2half2_rn(a.z, a.w));
    u.z = h2u(__floats2half2_rn(b.x, b.y));
    u.w = h2u(__floats2half2_rn(b.z, b.w));
    *(uint4*)(dst + i) = u;
}

// ---------------------------------------------------------------------------
// LayerNorm: one block per row, D = 1024, 256 threads. f16 output (GEMM A).
// ---------------------------------------------------------------------------
__global__ __launch_bounds__(256) void ln_kernel(
    const float* __restrict__ X, const float* __restrict__ w,
    const float* __restrict__ b, __half* __restrict__ out)
{
    long long row = blockIdx.x;
    const float* xr = X + row * Dx;
    int t = threadIdx.x;
    float4 v = *(const float4*)(xr + t * 4);
    float s  = v.x + v.y + v.z + v.w;
    float ss = v.x*v.x + v.y*v.y + v.z*v.z + v.w*v.w;
    #pragma unroll
    for (int o = 16; o > 0; o >>= 1) {
        s  += __shfl_xor_sync(0xffffffffu, s, o);
        ss += __shfl_xor_sync(0xffffffffu, ss, o);
    }
    __shared__ float rs[8], rss[8];
    __shared__ float smu, srstd;
    if ((t & 31) == 0) { rs[t >> 5] = s; rss[t >> 5] = ss; }
    __syncthreads();
    if (t == 0) {
        float S = 0.f, SS = 0.f;
        #pragma unroll
        for (int i = 0; i < 8; i++) { S += rs[i]; SS += rss[i]; }
        float mu  = S * (1.0f / Dx);
        float var = SS * (1.0f / Dx) - mu * mu;
        smu = mu; srstd = rsqrtf(var + 1e-5f);
    }
    __syncthreads();
    float mu = smu, r = srstd;
    float4 wv = *(const float4*)(w + t * 4);
    float4 bv = *(const float4*)(b + t * 4);
    uint2 u;
    u.x = h2u(__floats2half2_rn((v.x - mu) * r * wv.x + bv.x,
                                (v.y - mu) * r * wv.y + bv.y));
    u.y = h2u(__floats2half2_rn((v.z - mu) * r * wv.z + bv.z,
                                (v.w - mu) * r * wv.w + bv.w));
    *(uint2*)(out + row * Dx + t * 4) = u;
}

// ---------------------------------------------------------------------------
// Common PTX helpers
// ---------------------------------------------------------------------------
__device__ __forceinline__ float gelu_exact(float v) {
    return 0.5f * v * (1.0f + erff(v * 0.7071067811865476f));
}
__device__ __forceinline__ void cp16(uint32_t dst, const void* src) {
    asm volatile("cp.async.cg.shared.global [%0], [%1], 16;\n" :: "r"(dst), "l"(src));
}
__device__ __forceinline__ void ldsm4(uint32_t* r, uint32_t addr) {
    asm volatile("ldmatrix.sync.aligned.m8n8.x4.shared.b16 {%0,%1,%2,%3}, [%4];"
        : "=r"(r[0]), "=r"(r[1]), "=r"(r[2]), "=r"(r[3]) : "r"(addr));
}
__device__ __forceinline__ void ldsm4t(uint32_t* r, uint32_t addr) {
    asm volatile("ldmatrix.sync.aligned.m8n8.x4.trans.shared.b16 {%0,%1,%2,%3}, [%4];"
        : "=r"(r[0]), "=r"(r[1]), "=r"(r[2]), "=r"(r[3]) : "r"(addr));
}
__device__ __forceinline__ void mma_f16(float* d, const uint32_t* a, uint32_t b0, uint32_t b1) {
    asm volatile(
        "mma.sync.aligned.m16n8k16.row.col.f32.f16.f16.f32 "
        "{%0,%1,%2,%3}, {%4,%5,%6,%7}, {%8,%9}, {%0,%1,%2,%3};\n"
        : "+f"(d[0]), "+f"(d[1]), "+f"(d[2]), "+f"(d[3])
        : "r"(a[0]), "r"(a[1]), "r"(a[2]), "r"(a[3]),
          "r"(b0), "r"(b1));
}

// ---------------------------------------------------------------------------
// FP16 tensor-core GEMM: C[M,N] = A[M,K] @ W[K,N] + bias (+gelu) (+residual)
// 128x128 tile, BK=64, 3-stage cp.async, 256 threads, ldmatrix + m16n8k16.
// Dynamic smem 96KB: A stages [s*16KB], B stages [48KB + s*16KB].
// A tile [128][64]: byte = m*128 + ((c ^ (m&7))<<4) + (k&7)*2, c = k>>3
// B tile [64][128]: byte = k*256 + ((cn ^ (k&7))<<4) + (n&7)*2, cn = n>>3
// ---------------------------------------------------------------------------
__global__ __launch_bounds__(256) void gemm_f16(
    const __half* __restrict__ A, const __half* __restrict__ W,
    const float* __restrict__ bias, const float* __restrict__ resid,
    float* __restrict__ C, __half* __restrict__ Ch,
    int K, int N, int dogelu)
{
    extern __shared__ __half gsm[];

    const int tid  = threadIdx.x;
    const int lane = tid & 31;
    const int warp = tid >> 5;
    const int wm = (warp & 1) * 64;
    const int wn = (warp >> 1) * 32;
    const int gid = lane >> 2;
    const int tig = lane & 3;

    const int m0 = blockIdx.y * 128, n0 = blockIdx.x * 128;

    float acc[4][4][4];
    #pragma unroll
    for (int mt = 0; mt < 4; mt++)
        #pragma unroll
        for (int nt = 0; nt < 4; nt++)
            #pragma unroll
            for (int e = 0; e < 4; e++) acc[mt][nt][e] = 0.f;

    const uint32_t sbase = (uint32_t)__cvta_generic_to_shared(gsm);

    // Per-stage fill: A 1024 chunks + B 1024 chunks, 4+4 per thread
    #define PF(stg, kk0)                                                          \
    {                                                                             \
        _Pragma("unroll")                                                         \
        for (int i = 0; i < 4; i++) {                                             \
            int ch = tid + i * 256;                                               \
            int m = ch >> 3, c = ch & 7;                                          \
            cp16(sbase + (stg) * 16384 + m * 128 + ((c ^ (m & 7)) << 4),          \
                 A + (long long)(m0 + m) * K + (kk0) + c * 8);                    \
        }                                                                         \
        _Pragma("unroll")                                                         \
        for (int i = 0; i < 4; i++) {                                             \
            int ch = tid + i * 256;                                               \
            int k = ch >> 4, cn = ch & 15;                                        \
            cp16(sbase + 49152 + (stg) * 16384 + k * 256 + ((cn ^ (k & 7)) << 4), \
                 W + (long long)((kk0) + k) * N + n0 + cn * 8);                   \
        }                                                                         \
    }

    const int KT = K >> 6;
    PF(0, 0);
    asm volatile("cp.async.commit_group;\n");
    PF(1, 64);
    asm volatile("cp.async.commit_group;\n");

    const int lmat = lane >> 3, lrow = lane & 7;
    const int l15 = lane & 15;

    for (int kt = 0; kt < KT; kt++) {
        asm volatile("cp.async.wait_group 1;\n");
        __syncthreads();
        if (kt + 2 < KT) { PF((kt + 2) % 3, (kt + 2) * 64); }
        asm volatile("cp.async.commit_group;\n");

        const int stg = kt % 3;
        const uint32_t abase = sbase + stg * 16384;
        const uint32_t bbase = sbase + 49152 + stg * 16384;

        #pragma unroll
        for (int kk = 0; kk < 4; kk++) {
            uint32_t bf[4][2];
            #pragma unroll
            for (int p = 0; p < 2; p++) {
                int k = kk * 16 + (lmat & 1) * 8 + lrow;
                int cn = ((wn + p * 16) >> 3) + (lmat >> 1);
                uint32_t r[4];
                ldsm4t(r, bbase + k * 256 + ((cn ^ (k & 7)) << 4));
                bf[2 * p][0] = r[0]; bf[2 * p][1] = r[1];
                bf[2 * p + 1][0] = r[2]; bf[2 * p + 1][1] = r[3];
            }
            uint32_t af[4][4];
            #pragma unroll
            for (int mt = 0; mt < 4; mt++) {
                int m = wm + mt * 16 + l15;
                int c = kk * 2 + (lmat >> 1);
                ldsm4(af[mt], abase + m * 128 + ((c ^ (m & 7)) << 4));
            }
            #pragma unroll
            for (int mt = 0; mt < 4; mt++)
                #pragma unroll
                for (int nt = 0; nt < 4; nt++)
                    mma_f16(acc[mt][nt], af[mt], bf[nt][0], bf[nt][1]);
        }
    }

    #pragma unroll
    for (int mt = 0; mt < 4; mt++) {
        #pragma unroll
        for (int nt = 0; nt < 4; nt++) {
            int c = n0 + wn + nt * 8 + 2 * tig;
            float2 bv = *(const float2*)(bias + c);
            #pragma unroll
            for (int hh = 0; hh < 2; hh++) {
                long long r = m0 + wm + mt * 16 + gid + hh * 8;
                float2 v;
                v.x = acc[mt][nt][2 * hh + 0] + bv.x;
                v.y = acc[mt][nt][2 * hh + 1] + bv.y;
                if (dogelu) { v.x = gelu_exact(v.x); v.y = gelu_exact(v.y); }
                if (resid) {
                    float2 rv = *(const float2*)(resid + r * N + c);
                    v.x += rv.x; v.y += rv.y;
                }
                if (C)  *(float2*)(C + r * N + c) = v;
                if (Ch) *(__half2*)(Ch + r * N + c) = __floats2half2_rn(v.x, v.y);
            }
        }
    }
}

// ---------------------------------------------------------------------------
// Tensor-core fp16 flash attention (unchanged from R6 — proven).
// Block = (b,h) x 64-query tile; 128 threads (4 warps x 16 rows).
// ---------------------------------------------------------------------------
__global__ __launch_bounds__(128) void attn_f16(
    const __half* __restrict__ Qp, int ldq, long long qbs,
    const __half* __restrict__ Kp, int ldk, long long kbs,
    const __half* __restrict__ Vp, int ldv, long long vbs,
    __half* __restrict__ Op, int ldo, long long obs,
    const int* __restrict__ maskp, int Mk, int causal)
{
    __shared__ __half Qs[64 * 64];
    __shared__ __half Ks[2][64 * 64];
    __shared__ __half Vs[2][64 * 64];
    __shared__ int    msks[2][64];

    const int tid  = threadIdx.x;
    const int lane = tid & 31;
    const int warp = tid >> 5;
    const int l15 = lane & 15, l16 = lane >> 4, l7 = lane & 7;
    const int gid = lane >> 2, tig = lane & 3;

    const int b = blockIdx.x >> 4, h = blockIdx.x & 15;
    const int q0 = blockIdx.y * 64;

    const __half* Q  = Qp + b * qbs + h * 64;
    const __half* Kb = Kp + b * kbs + h * 64;
    const __half* Vb = Vp + b * vbs + h * 64;
    const int*    mk = maskp ? (maskp + (long long)b * Mk) : (const int*)0;

    const uint32_t qbase = (uint32_t)__cvta_generic_to_shared(Qs);
    const uint32_t kbase = (uint32_t)__cvta_generic_to_shared(&Ks[0][0]);
    const uint32_t vbase = (uint32_t)__cvta_generic_to_shared(&Vs[0][0]);
    const uint32_t mbase = (uint32_t)__cvta_generic_to_shared(&msks[0][0]);

    #define PFKV(stg, key0)                                                        \
    {                                                                              \
        _Pragma("unroll")                                                          \
        for (int p = 0; p < 4; p++) {                                              \
            int ch = tid + p * 128;                                                \
            int r = ch >> 3, c = ch & 7;                                           \
            uint32_t so = r * 128 + ((c ^ (r & 7)) << 4);                          \
            cp16(kbase + (stg) * 8192 + so, Kb + (long long)((key0) + r) * ldk + c * 8); \
            cp16(vbase + (stg) * 8192 + so, Vb + (long long)((key0) + r) * ldv + c * 8); \
        }                                                                          \
        if (mk && tid < 16)                                                        \
            cp16(mbase + (stg) * 256 + tid * 16, mk + (key0) + tid * 4);           \
    }

    #pragma unroll
    for (int p = 0; p < 4; p++) {
        int ch = tid + p * 128;
        int r = ch >> 3, c = ch & 7;
        cp16(qbase + r * 128 + ((c ^ (r & 7)) << 4),
             Q + (long long)(q0 + r) * ldq + c * 8);
    }
    PFKV(0, 0);
    asm volatile("cp.async.commit_group;\n");

    float m_i[2] = {-1e30f, -1e30f}, l_i[2] = {0.f, 0.f};
    float oacc[8][4];
    #pragma unroll
    for (int dt = 0; dt < 8; dt++)
        #pragma unroll
        for (int e = 0; e < 4; e++) oacc[dt][e] = 0.f;

    const int nkt = causal ? (blockIdx.y + 1) : (Mk >> 6);
    const int row0 = q0 + 16 * warp + gid;

    for (int kt = 0; kt < nkt; kt++) {
        if (kt + 1 < nkt) {
            PFKV((kt + 1) & 1, (kt + 1) * 64);
            asm volatile("cp.async.commit_group;\n");
            asm volatile("cp.async.wait_group 1;\n");
        } else {
            asm volatile("cp.async.wait_group 0;\n");
        }
        __syncthreads();

        const int stg = kt & 1;
        const uint32_t kb = kbase + stg * 8192;
        const uint32_t vb = vbase + stg * 8192;
        const int k0 = kt * 64;

        float sc[8][4];
        #pragma unroll
        for (int nt = 0; nt < 8; nt++)
            #pragma unroll
            for (int e = 0; e < 4; e++) sc[nt][e] = 0.f;

        #pragma unroll
        for (int kk = 0; kk < 4; kk++) {
            uint32_t af[4];
            ldsm4(af, qbase + (16 * warp + l15) * 128 + (((2 * kk + l16) ^ l7) << 4));
            #pragma unroll
            for (int ng = 0; ng < 4; ng++) {
                uint32_t bf[4];
                ldsm4(bf, kb + (16 * ng + l15) * 128 + (((2 * kk + l16) ^ l7) << 4));
                mma_f16(sc[2 * ng],     af, bf[0], bf[2]);
                mma_f16(sc[2 * ng + 1], af, bf[1], bf[3]);
            }
        }

        const bool diag = (causal != 0) && (kt == blockIdx.y);
        #pragma unroll
        for (int nt = 0; nt < 8; nt++) {
            #pragma unroll
            for (int e = 0; e < 4; e++) sc[nt][e] *= 0.125f;
            int key0 = nt * 8 + 2 * tig;
            if (mk) {
                if (!msks[stg][key0])     { sc[nt][0] = NEGINF; sc[nt][2] = NEGINF; }
                if (!msks[stg][key0 + 1]) { sc[nt][1] = NEGINF; sc[nt][3] = NEGINF; }
            }
            if (diag) {
                int gk0 = k0 + key0, gk1 = gk0 + 1;
                if (gk0 > row0)     sc[nt][0] = NEGINF;
                if (gk1 > row0)     sc[nt][1] = NEGINF;
                if (gk0 > row0 + 8) sc[nt][2] = NEGINF;
                if (gk1 > row0 + 8) sc[nt][3] = NEGINF;
            }
        }

        float rmax0 = -1e30f, rmax1 = -1e30f;
        #pragma unroll
        for (int nt = 0; nt < 8; nt++) {
            rmax0 = fmaxf(rmax0, fmaxf(sc[nt][0], sc[nt][1]));
            rmax1 = fmaxf(rmax1, fmaxf(sc[nt][2], sc[nt][3]));
        }
        rmax0 = fmaxf(rmax0, __shfl_xor_sync(0xffffffffu, rmax0, 1));
        rmax0 = fmaxf(rmax0, __shfl_xor_sync(0xffffffffu, rmax0, 2));
        rmax1 = fmaxf(rmax1, __shfl_xor_sync(0xffffffffu, rmax1, 1));
        rmax1 = fmaxf(rmax1, __shfl_xor_sync(0xffffffffu, rmax1, 2));

        float mn0 = fmaxf(m_i[0], rmax0), mn1 = fmaxf(m_i[1], rmax1);
        float sc0 = __expf(m_i[0] - mn0), sc1 = __expf(m_i[1] - mn1);
        float rs0 = 0.f, rs1 = 0.f;
        uint32_t p01[8], p23[8];
        #pragma unroll
        for (int nt = 0; nt < 8; nt++) {
            float e0 = __expf(sc[nt][0] - mn0);
            float e1 = __expf(sc[nt][1] - mn0);
            float e2 = __expf(sc[nt][2] - mn1);
            float e3 = __expf(sc[nt][3] - mn1);
            rs0 += e0 + e1; rs1 += e2 + e3;
            p01[nt] = h2u(__floats2half2_rn(e0, e1));
            p23[nt] = h2u(__floats2half2_rn(e2, e3));
        }
        rs0 += __shfl_xor_sync(0xffffffffu, rs0, 1);
        rs0 += __shfl_xor_sync(0xffffffffu, rs0, 2);
        rs1 += __shfl_xor_sync(0xffffffffu, rs1, 1);
        rs1 += __shfl_xor_sync(0xffffffffu, rs1, 2);

        l_i[0] = l_i[0] * sc0 + rs0;
        l_i[1] = l_i[1] * sc1 + rs1;
        m_i[0] = mn0; m_i[1] = mn1;
        #pragma unroll
        for (int dt = 0; dt < 8; dt++) {
            oacc[dt][0] *= sc0; oacc[dt][1] *= sc0;
            oacc[dt][2] *= sc1; oacc[dt][3] *= sc1;
        }

        #pragma unroll
        for (int j = 0; j < 4; j++) {
            uint32_t a[4] = { p01[2 * j], p23[2 * j], p01[2 * j + 1], p23[2 * j + 1] };
            #pragma unroll
            for (int g = 0; g < 4; g++) {
                uint32_t bf[4];
                ldsm4t(bf, vb + (16 * j + l15) * 128 + (((2 * g + l16) ^ l7) << 4));
                mma_f16(oacc[2 * g],     a, bf[0], bf[1]);
                mma_f16(oacc[2 * g + 1], a, bf[2], bf[3]);
            }
        }
        __syncthreads();
    }

    float inv0 = 1.0f / l_i[0], inv1 = 1.0f / l_i[1];
    #pragma unroll
    for (int dt = 0; dt < 8; dt++) {
        int col = h * 64 + dt * 8 + 2 * tig;
        *(__half2*)(Op + b * obs + (long long)row0 * ldo + col) =
            __floats2half2_rn(oacc[dt][0] * inv0, oacc[dt][1] * inv0);
        *(__half2*)(Op + b * obs + (long long)(row0 + 8) * ldo + col) =
            __floats2half2_rn(oacc[dt][2] * inv1, oacc[dt][3] * inv1);
    }
}

// ---------------------------------------------------------------------------
// Launch: graph-capturable; main stream + one forked side stream (events).
// Side stream handles cvts not needed immediately + the independent kv GEMM,
// fully hidden under LN1 -> qkv GEMM -> self-attention on the main stream.
// ---------------------------------------------------------------------------
extern "C" void kernel_launch(void* const* d_in, const int* in_sizes, int n_in,
                              void* d_out, int out_size)
{
    const float* x         = (const float*)d_in[0];
    const float* mem       = (const float*)d_in[1];
    const int*   mem_mask  = (const int*)  d_in[2];
    const float* ln1_w     = (const float*)d_in[3];
    const float* ln1_b     = (const float*)d_in[4];
    const float* sa_qkv_w  = (const float*)d_in[5];
    const float* sa_qkv_b  = (const float*)d_in[6];
    const float* sa_proj_w = (const float*)d_in[7];
    const float* sa_proj_b = (const float*)d_in[8];
    const float* lnm_w     = (const float*)d_in[9];
    const float* lnm_b     = (const float*)d_in[10];
    const float* ca_q_w    = (const float*)d_in[11];
    const float* ca_q_b    = (const float*)d_in[12];
    const float* ca_kv_w   = (const float*)d_in[13];
    const float* ca_kv_b   = (const float*)d_in[14];
    const float* ca_proj_w = (const float*)d_in[15];
    const float* ca_proj_b = (const float*)d_in[16];
    const float* ln2_w     = (const float*)d_in[17];
    const float* ln2_b     = (const float*)d_in[18];
    const float* ff1_w     = (const float*)d_in[19];
    const float* ff1_b     = (const float*)d_in[20];
    const float* ff2_w     = (const float*)d_in[21];
    const float* ff2_b     = (const float*)d_in[22];
    float* out = (float*)d_out;

    float *xr;
    __half *qkvh, *qch, *kvh, *hh, *yh, *ych, *ffh, *wh, *memh;
    cudaGetSymbolAddress((void**)&xr,   g_x);
    cudaGetSymbolAddress((void**)&qkvh, g_qkvh);
    cudaGetSymbolAddress((void**)&qch,  g_qch);
    cudaGetSymbolAddress((void**)&kvh,  g_kvh);
    cudaGetSymbolAddress((void**)&hh,   g_hh);
    cudaGetSymbolAddress((void**)&yh,   g_yh);
    cudaGetSymbolAddress((void**)&ych,  g_ych);
    cudaGetSymbolAddress((void**)&ffh,  g_ffh);
    cudaGetSymbolAddress((void**)&wh,   g_wh);
    cudaGetSymbolAddress((void**)&memh, g_memh);

    // Allow 96KB dynamic smem for the GEMM (host-side attr; capture-safe)
    cudaFuncSetAttribute(gemm_f16, cudaFuncAttributeMaxDynamicSharedMemorySize, GEMM_DSMEM);

    // Fork a side stream off the capture (legacy) stream via events
    cudaStream_t s1;
    cudaStreamCreate(&s1);
    cudaEvent_t eFork, ePre, eKV;
    cudaEventCreateWithFlags(&eFork, cudaEventDisableTiming);
    cudaEventCreateWithFlags(&ePre,  cudaEventDisableTiming);
    cudaEventCreateWithFlags(&eKV,   cudaEventDisableTiming);

    cudaEventRecord(eFork, 0);
    cudaStreamWaitEvent(s1, eFork, 0);

    // ---- side stream: deferred weight cvts + independent kv path ----
    cvt_h_kernel<<<Dx * Dx / 2048,     256, 0, s1>>>(sa_proj_w, wh + WOFF_PROJ);
    cvt_h_kernel<<<Dx * Dx / 2048,     256, 0, s1>>>(ca_q_w,    wh + WOFF_CAQ);
    cvt_h_kernel<<<Dx * Dx / 2048,     256, 0, s1>>>(ca_proj_w, wh + WOFF_CAPROJ);
    cvt_h_kernel<<<Dx * DFFx / 2048,   256, 0, s1>>>(ff1_w,     wh + WOFF_FF1);
    cvt_h_kernel<<<DFFx * Dx / 2048,   256, 0, s1>>>(ff2_w,     wh + WOFF_FF2);
    cvt_h_kernel<<<NM * Dx / 2048,     256, 0, s1>>>(mem,       memh);
    cvt_h_kernel<<<2 * Dx * Dx / 2048, 256, 0, s1>>>(ca_kv_w,   wh + WOFF_CAKV);
    cudaEventRecord(ePre, s1);   // all deferred cvts done
    // kv = mem @ Wkv + b (f16) — independent of the self-attn path
    gemm_f16<<<dim3(2 * Dx / 128, NM / 128), 256, GEMM_DSMEM, s1>>>(
        memh, wh + WOFF_CAKV, ca_kv_b, 0, 0, kvh, Dx, 2 * Dx, 0);
    cudaEventRecord(eKV, s1);

    // ---- main stream ----
    // cvt needed immediately
    cvt_h_kernel<<<3 * Dx * Dx / 2048, 256>>>(sa_qkv_w, wh + WOFF_QKV);
    // 1) hh = LN(x)
    ln_kernel<<<NX, 256>>>(x, ln1_w, ln1_b, hh);
    // 2) qkvh = hh @ Wqkv + b (f16)
    gemm_f16<<<dim3(3 * Dx / 128, NX / 128), 256, GEMM_DSMEM>>>(
        hh, wh + WOFF_QKV, sa_qkv_b, 0, 0, qkvh, Dx, 3 * Dx, 0);
    // 3) yh = causal self-attention(qkvh)
    attn_f16<<<dim3(Bx * Hx, Tx / 64), 128>>>(
        qkvh,          3 * Dx, (long long)Tx * 3 * Dx,
        qkvh + Dx,     3 * Dx, (long long)Tx * 3 * Dx,
        qkvh + 2 * Dx, 3 * Dx, (long long)Tx * 3 * Dx,
        yh,            Dx,     (long long)Tx * Dx,
        (const int*)0, Tx, 1);
    // join: deferred cvts (proj weight needed next)
    cudaStreamWaitEvent(0, ePre, 0);
    // 4) x1 = x + yh @ Wproj + b
    gemm_f16<<<dim3(Dx / 128, NX / 128), 256, GEMM_DSMEM>>>(
        yh, wh + WOFF_PROJ, sa_proj_b, x, xr, 0, Dx, Dx, 0);
    // 5) hh = LN(x1)
    ln_kernel<<<NX, 256>>>(xr, lnm_w, lnm_b, hh);
    // 6) qch = hh @ Wq + b (f16)
    gemm_f16<<<dim3(Dx / 128, NX / 128), 256, GEMM_DSMEM>>>(
        hh, wh + WOFF_CAQ, ca_q_b, 0, 0, qch, Dx, Dx, 0);
    // join: kv GEMM result needed for cross-attention
    cudaStreamWaitEvent(0, eKV, 0);
    // 8) ych = cross-attention(qch, kvh, mem_mask)
    attn_f16<<<dim3(Bx * Hx, Tx / 64), 128>>>(
        qch,       Dx,     (long long)Tx * Dx,
        kvh,       2 * Dx, (long long)Mx * 2 * Dx,
        kvh + Dx,  2 * Dx, (long long)Mx * 2 * Dx,
        ych,       Dx,     (long long)Tx * Dx,
        mem_mask, Mx, 0);
    // 9) x2 = x1 + ych @ Wcp + b (in-place residual)
    gemm_f16<<<dim3(Dx / 128, NX / 128), 256, GEMM_DSMEM>>>(
        ych, wh + WOFF_CAPROJ, ca_proj_b, xr, xr, 0, Dx, Dx, 0);
    // 10) hh = LN(x2)
    ln_kernel<<<NX, 256>>>(xr, ln2_w, ln2_b, hh);
    // 11) ffh = gelu(hh @ W1 + b)
    gemm_f16<<<dim3(DFFx / 128, NX / 128), 256, GEMM_DSMEM>>>(
        hh, wh + WOFF_FF1, ff1_b, 0, 0, ffh, Dx, DFFx, 1);
    // 12) out = x2 + ffh @ W2 + b (fp32 final)
    gemm_f16<<<dim3(Dx / 128, NX / 128), 256, GEMM_DSMEM>>>(
        ffh, wh + WOFF_FF2, ff2_b, xr, out, 0, DFFx, Dx, 0);
}